// round 1
// baseline (speedup 1.0000x reference)
#include <cuda_runtime.h>
#include <cstdint>
#include <cstdio>

// ---------------- problem constants ----------------
#define BB     8
#define NQL    2048
#define ISZ    1024
#define HH     8
#define DDIM   128
#define NAA    8
#define AHD    1024      // H*D
#define FHD    4096
#define MROWS  (BB*NQL)  // 16384
#define SCALE_D 0.08838834764831845f  // 1/sqrt(128)

// ---------------- scratch (static device allocations; no runtime alloc) ----------------
__device__ float g_x   [(size_t)MROWS * ISZ];        // 64 MB  normalized input
__device__ float g_qkv [(size_t)MROWS * 3 * AHD];    // 192 MB qkv
__device__ float g_att1[BB * HH * NAA * DDIM];       // attention-1 output [B,H,NA,D]
__device__ float g_netin[BB * NAA * FHD];            // permuted relu(att1@W_an)
__device__ float g_n1  [BB * NAA * AHD];
__device__ float g_n2  [BB * NAA * FHD];
__device__ float g_out3[BB * NAA * AHD];             // "out" after W_n3 (= ov)
__device__ float g_kkb [BB * NAA * AHD];             // kk
__device__ float g_y   [(size_t)MROWS * AHD];        // 64 MB
__device__ float g_part[8 * 64 * 4096];              // split-K partials (S=8)

// ---------------- LayerNorm: one block per row ----------------
__global__ __launch_bounds__(256) void ln_kernel(const float* __restrict__ in,
                                                 const float* __restrict__ gam,
                                                 const float* __restrict__ bet) {
    int row = blockIdx.x;
    int tid = threadIdx.x;
    const float4 v = ((const float4*)(in + (size_t)row * ISZ))[tid];
    float s  = v.x + v.y + v.z + v.w;
    float ss = v.x*v.x + v.y*v.y + v.z*v.z + v.w*v.w;
    __shared__ float r1[32], r2[32];
    #pragma unroll
    for (int o = 16; o; o >>= 1) {
        s  += __shfl_xor_sync(0xffffffffu, s,  o);
        ss += __shfl_xor_sync(0xffffffffu, ss, o);
    }
    if ((tid & 31) == 0) { r1[tid >> 5] = s; r2[tid >> 5] = ss; }
    __syncthreads();
    if (tid < 32) {
        float a = (tid < 8) ? r1[tid] : 0.f;
        float b = (tid < 8) ? r2[tid] : 0.f;
        #pragma unroll
        for (int o = 4; o; o >>= 1) {
            a += __shfl_xor_sync(0xffffffffu, a, o);
            b += __shfl_xor_sync(0xffffffffu, b, o);
        }
        if (tid == 0) { r1[0] = a; r2[0] = b; }
    }
    __syncthreads();
    float mean = r1[0] * (1.0f / ISZ);
    float var  = r2[0] * (1.0f / ISZ) - mean * mean;
    float rstd = rsqrtf(var + 1e-6f);
    const float4 g4 = ((const float4*)gam)[tid];
    const float4 b4 = ((const float4*)bet)[tid];
    float4 o;
    o.x = (v.x - mean) * rstd * g4.x + b4.x;
    o.y = (v.y - mean) * rstd * g4.y + b4.y;
    o.z = (v.z - mean) * rstd * g4.z + b4.z;
    o.w = (v.w - mean) * rstd * g4.w + b4.w;
    ((float4*)(g_x + (size_t)row * ISZ))[tid] = o;
}

// ---------------- big SGEMM: 128x128 tiles, 8x8/thread, M,N%128==0, K%8==0 ----------------
__global__ __launch_bounds__(256, 2)
void sgemm128(int M, int N, int K,
              const float* __restrict__ A,   // MxK row-major
              const float* __restrict__ B,   // KxN row-major
              const float* __restrict__ bias,
              const float* __restrict__ resid,  // MxN or null
              float* __restrict__ C, int act) {
    __shared__ __align__(16) float As[8][132];
    __shared__ __align__(16) float Bs[8][128];
    const int tid = threadIdx.x;
    const int bx = blockIdx.x, by = blockIdx.y;
    const int tx = tid & 15, ty = tid >> 4;
    const int aRow = tid >> 1;            // 0..127
    const int aK   = (tid & 1) * 4;       // 0 or 4
    const int bRow = tid >> 5;            // 0..7
    const int bCol = (tid & 31) * 4;      // 0..124
    const float* Aptr = A + (size_t)(by * 128 + aRow) * K + aK;
    const float* Bptr = B + (size_t)bRow * N + bx * 128 + bCol;

    float acc[8][8];
    #pragma unroll
    for (int i = 0; i < 8; i++)
        #pragma unroll
        for (int j = 0; j < 8; j++) acc[i][j] = 0.f;

    float4 a4 = *(const float4*)Aptr;
    float4 b4 = *(const float4*)Bptr;
    for (int k0 = 0; k0 < K; k0 += 8) {
        As[aK + 0][aRow] = a4.x;
        As[aK + 1][aRow] = a4.y;
        As[aK + 2][aRow] = a4.z;
        As[aK + 3][aRow] = a4.w;
        *(float4*)&Bs[bRow][bCol] = b4;
        __syncthreads();
        if (k0 + 8 < K) {
            a4 = *(const float4*)(Aptr + k0 + 8);
            b4 = *(const float4*)(Bptr + (size_t)(k0 + 8) * N);
        }
        #pragma unroll
        for (int kk = 0; kk < 8; kk++) {
            float4 ra0 = *(const float4*)&As[kk][ty * 8];
            float4 ra1 = *(const float4*)&As[kk][ty * 8 + 4];
            float4 rb0 = *(const float4*)&Bs[kk][tx * 8];
            float4 rb1 = *(const float4*)&Bs[kk][tx * 8 + 4];
            float ra[8] = {ra0.x, ra0.y, ra0.z, ra0.w, ra1.x, ra1.y, ra1.z, ra1.w};
            float rb[8] = {rb0.x, rb0.y, rb0.z, rb0.w, rb1.x, rb1.y, rb1.z, rb1.w};
            #pragma unroll
            for (int i = 0; i < 8; i++)
                #pragma unroll
                for (int j = 0; j < 8; j++) acc[i][j] += ra[i] * rb[j];
        }
        __syncthreads();
    }
    // epilogue
    const int col0 = bx * 128 + tx * 8;
    float bb[8];
    #pragma unroll
    for (int j = 0; j < 8; j++) bb[j] = bias ? bias[col0 + j] : 0.f;
    #pragma unroll
    for (int i = 0; i < 8; i++) {
        int r = by * 128 + ty * 8 + i;
        float* crow = C + (size_t)r * N + col0;
        float out[8];
        #pragma unroll
        for (int j = 0; j < 8; j++) {
            float v = acc[i][j] + bb[j];
            out[j] = v;
        }
        if (resid) {
            const float* rr = resid + (size_t)r * N + col0;
            float4 r0 = *(const float4*)rr;
            float4 r1 = *(const float4*)(rr + 4);
            out[0] += r0.x; out[1] += r0.y; out[2] += r0.z; out[3] += r0.w;
            out[4] += r1.x; out[5] += r1.y; out[6] += r1.z; out[7] += r1.w;
        }
        if (act) {
            #pragma unroll
            for (int j = 0; j < 8; j++) out[j] = fmaxf(out[j], 0.f);
        }
        *(float4*)crow       = make_float4(out[0], out[1], out[2], out[3]);
        *(float4*)(crow + 4) = make_float4(out[4], out[5], out[6], out[7]);
    }
}

// ---------------- split-K SGEMM for skinny M=64 middle GEMMs ----------------
// grid: (N/64, 1, 8).  Writes partials to g_part[z][64][N]. N%64==0, K%64==0.
__global__ __launch_bounds__(256)
void sgemm_splitk64(int N, int K, int kc,
                    const float* __restrict__ A,   // 64 x K
                    const float* __restrict__ B,   // K x N
                    float* __restrict__ part) {
    __shared__ __align__(16) float As[8][68];
    __shared__ __align__(16) float Bs[8][64];
    const int tid = threadIdx.x;
    const int bx = blockIdx.x, z = blockIdx.z;
    const int tx = tid & 15, ty = tid >> 4;
    const int aRow = tid >> 2;           // 0..63
    const int aK   = (tid & 3) * 2;      // 0,2,4,6
    const int bRow = tid >> 5;           // 0..7
    const int bCol = (tid & 31) * 2;     // 0..62
    const int kb = z * kc;

    float acc[4][4];
    #pragma unroll
    for (int i = 0; i < 4; i++)
        #pragma unroll
        for (int j = 0; j < 4; j++) acc[i][j] = 0.f;

    for (int k0 = kb; k0 < kb + kc; k0 += 8) {
        float2 a2 = *(const float2*)(A + (size_t)aRow * K + k0 + aK);
        float2 b2 = *(const float2*)(B + (size_t)(k0 + bRow) * N + bx * 64 + bCol);
        __syncthreads();
        As[aK][aRow] = a2.x; As[aK + 1][aRow] = a2.y;
        Bs[bRow][bCol] = b2.x; Bs[bRow][bCol + 1] = b2.y;
        __syncthreads();
        #pragma unroll
        for (int kk = 0; kk < 8; kk++) {
            float ra[4], rb[4];
            #pragma unroll
            for (int i = 0; i < 4; i++) ra[i] = As[kk][ty * 4 + i];
            #pragma unroll
            for (int j = 0; j < 4; j++) rb[j] = Bs[kk][tx * 4 + j];
            #pragma unroll
            for (int i = 0; i < 4; i++)
                #pragma unroll
                for (int j = 0; j < 4; j++) acc[i][j] += ra[i] * rb[j];
        }
    }
    #pragma unroll
    for (int i = 0; i < 4; i++) {
        float* p = part + (size_t)z * 64 * N + (size_t)(ty * 4 + i) * N + bx * 64 + tx * 4;
        *(float4*)p = make_float4(acc[i][0], acc[i][1], acc[i][2], acc[i][3]);
    }
}

// sum 8 split-K partials + bias (+relu) (+permute for the W_an output)
__global__ __launch_bounds__(256)
void reduce_bias_act(const float* __restrict__ part, const float* __restrict__ bias,
                     float* __restrict__ out, int N, int act, int permute) {
    int idx = blockIdx.x * 256 + threadIdx.x;
    int total = 64 * N;
    if (idx >= total) return;
    int m = idx / N, n = idx - m * N;
    float s = 0.f;
    #pragma unroll
    for (int z = 0; z < 8; z++) s += part[(size_t)z * total + idx];
    s += bias[n];
    if (act) s = fmaxf(s, 0.f);
    if (permute) {
        // in:  [b, h, na*512 + j]   out: [b, na, h*512 + j]
        int b = m >> 3, h = m & 7;
        int na = n >> 9, j = n & 511;
        out[((size_t)(b * 8 + na)) * 4096 + h * 512 + j] = s;
    } else {
        out[idx] = s;
    }
}

// ---------------- attention 1: block per (b,h,a); logits+softmax+AV fused ----------------
__global__ __launch_bounds__(256) void attn1_kernel(const float* __restrict__ q_anchor) {
    const int a = blockIdx.x & 7;
    const int h = (blockIdx.x >> 3) & 7;
    const int b = blockIdx.x >> 6;
    const int tid = threadIdx.x;  // 256
    __shared__ __align__(16) float qas[128];
    __shared__ float probs[2048];
    __shared__ float red[32];
    __shared__ float accsh[128];
    __shared__ float Mv, Sv;

    if (tid < 128) qas[tid] = q_anchor[(h * 8 + a) * 128 + tid];
    __syncthreads();

    float loc[8];
    float lmax = -1e30f;
    #pragma unroll
    for (int i = 0; i < 8; i++) {
        int n = i * 256 + tid;
        const float4* kr = (const float4*)(g_qkv + (((size_t)(b * NQL + n)) * 3 + 1) * AHD + h * DDIM);
        float s = 0.f;
        #pragma unroll
        for (int j = 0; j < 32; j++) {
            float4 kv = kr[j];
            float4 qv = ((const float4*)qas)[j];
            s += kv.x * qv.x + kv.y * qv.y + kv.z * qv.z + kv.w * qv.w;
        }
        loc[i] = s * SCALE_D;
        lmax = fmaxf(lmax, loc[i]);
    }
    // block max
    float m = lmax;
    #pragma unroll
    for (int o = 16; o; o >>= 1) m = fmaxf(m, __shfl_xor_sync(0xffffffffu, m, o));
    if ((tid & 31) == 0) red[tid >> 5] = m;
    __syncthreads();
    if (tid < 32) {
        float t = (tid < 8) ? red[tid] : -1e30f;
        #pragma unroll
        for (int o = 4; o; o >>= 1) t = fmaxf(t, __shfl_xor_sync(0xffffffffu, t, o));
        if (tid == 0) Mv = t;
    }
    __syncthreads();
    const float gm = Mv;
    float lsum = 0.f;
    #pragma unroll
    for (int i = 0; i < 8; i++) {
        float e = __expf(loc[i] - gm);
        probs[i * 256 + tid] = e;
        lsum += e;
    }
    // block sum
    #pragma unroll
    for (int o = 16; o; o >>= 1) lsum += __shfl_xor_sync(0xffffffffu, lsum, o);
    __syncthreads();  // red[] reuse
    if ((tid & 31) == 0) red[tid >> 5] = lsum;
    __syncthreads();
    if (tid < 32) {
        float t = (tid < 8) ? red[tid] : 0.f;
        #pragma unroll
        for (int o = 4; o; o >>= 1) t += __shfl_xor_sync(0xffffffffu, t, o);
        if (tid == 0) Sv = t;
    }
    __syncthreads();

    // AV: thread (d, half) accumulates half the sequence
    const int d = tid & 127;
    const int half = tid >> 7;
    float acc = 0.f;
    const int n0 = half * 1024;
    for (int n = n0; n < n0 + 1024; n++) {
        float v = g_qkv[(((size_t)(b * NQL + n)) * 3 + 2) * AHD + h * DDIM + d];
        acc += probs[n] * v;
    }
    if (half) accsh[d] = acc;
    __syncthreads();
    if (!half)
        g_att1[(((size_t)(b * 8 + h)) * 8 + a) * 128 + d] = (acc + accsh[d]) / Sv;
}

// ---------------- attention 2 + y: block per (b,h,128 q-rows) ----------------
__global__ __launch_bounds__(128) void attn2_kernel() {
    const int nc = blockIdx.x;   // 0..15
    const int h  = blockIdx.y;
    const int b  = blockIdx.z;
    const int tid = threadIdx.x; // 128
    __shared__ __align__(16) float kks[8][128];
    __shared__ __align__(16) float ovs[8][128];
    __shared__ float ps[128][9];

    #pragma unroll
    for (int r = 0; r < 8; r++) {
        kks[r][tid] = g_kkb [((size_t)(b * 8 + r)) * AHD + h * 128 + tid];
        ovs[r][tid] = g_out3[((size_t)(b * 8 + r)) * AHD + h * 128 + tid];
    }
    __syncthreads();

    const int n = nc * 128 + tid;
    const float4* qr = (const float4*)(g_qkv + ((size_t)(b * NQL + n)) * 3 * AHD + h * 128);
    float lg[8];
    #pragma unroll
    for (int aa = 0; aa < 8; aa++) lg[aa] = 0.f;
    #pragma unroll
    for (int j = 0; j < 32; j++) {
        float4 qv = qr[j];
        #pragma unroll
        for (int aa = 0; aa < 8; aa++) {
            float4 kv = ((const float4*)kks[aa])[j];
            lg[aa] += qv.x * kv.x + qv.y * kv.y + qv.z * kv.z + qv.w * kv.w;
        }
    }
    float m = -1e30f;
    #pragma unroll
    for (int aa = 0; aa < 8; aa++) { lg[aa] *= SCALE_D; m = fmaxf(m, lg[aa]); }
    float s = 0.f;
    #pragma unroll
    for (int aa = 0; aa < 8; aa++) { lg[aa] = __expf(lg[aa] - m); s += lg[aa]; }
    float inv = 1.0f / s;
    #pragma unroll
    for (int aa = 0; aa < 8; aa++) ps[tid][aa] = lg[aa] * inv;
    __syncthreads();

    for (int i = 0; i < 128; i++) {
        float acc = 0.f;
        #pragma unroll
        for (int aa = 0; aa < 8; aa++) acc += ps[i][aa] * ovs[aa][tid];
        g_y[((size_t)(b * NQL) + nc * 128 + i) * AHD + h * 128 + tid] = acc;
    }
}

// ---------------- host orchestration ----------------
extern "C" void kernel_launch(void* const* d_in, const int* in_sizes, int n_in,
                              void* d_out, int out_size) {
    (void)in_sizes; (void)n_in; (void)out_size;
    const float* inputs   = (const float*)d_in[0];
    const float* ln_g     = (const float*)d_in[1];
    const float* ln_b     = (const float*)d_in[2];
    const float* q_anchor = (const float*)d_in[3];
    const float* W_qkv    = (const float*)d_in[4];
    const float* b_qkv    = (const float*)d_in[5];
    const float* W_an     = (const float*)d_in[6];
    const float* b_an     = (const float*)d_in[7];
    const float* W_n1     = (const float*)d_in[8];
    const float* b_n1     = (const float*)d_in[9];
    const float* W_n2     = (const float*)d_in[10];
    const float* b_n2     = (const float*)d_in[11];
    const float* W_n3     = (const float*)d_in[12];
    const float* b_n3     = (const float*)d_in[13];
    const float* W_k      = (const float*)d_in[14];
    const float* b_k      = (const float*)d_in[15];
    const float* W_o      = (const float*)d_in[16];
    const float* b_o      = (const float*)d_in[17];
    float* out = (float*)d_out;

    float *x, *qkv, *att1, *netin, *n1, *n2, *out3, *kk, *y, *part;
    cudaGetSymbolAddress((void**)&x,    g_x);
    cudaGetSymbolAddress((void**)&qkv,  g_qkv);
    cudaGetSymbolAddress((void**)&att1, g_att1);
    cudaGetSymbolAddress((void**)&netin,g_netin);
    cudaGetSymbolAddress((void**)&n1,   g_n1);
    cudaGetSymbolAddress((void**)&n2,   g_n2);
    cudaGetSymbolAddress((void**)&out3, g_out3);
    cudaGetSymbolAddress((void**)&kk,   g_kkb);
    cudaGetSymbolAddress((void**)&y,    g_y);
    cudaGetSymbolAddress((void**)&part, g_part);

    // 1. LayerNorm
    ln_kernel<<<MROWS, 256>>>(inputs, ln_g, ln_b);

    // 2. qkv = x @ W_qkv + b_qkv   (16384 x 3072 x 1024)
    sgemm128<<<dim3(3072 / 128, MROWS / 128), 256>>>(MROWS, 3072, 1024, x, W_qkv, b_qkv, nullptr, qkv, 0);

    // 3. attention 1 -> g_att1 [B,H,NA,D]
    attn1_kernel<<<BB * HH * NAA, 256>>>(q_anchor);

    // 4. relu(att1 @ W_an + b_an) with permute -> g_netin [B,NA,4096]
    sgemm_splitk64<<<dim3(4096 / 64, 1, 8), 256>>>(4096, 1024, 128, att1, W_an, part);
    reduce_bias_act<<<(64 * 4096 + 255) / 256, 256>>>(part, b_an, netin, 4096, 1, 1);

    // 5. n1 = netin @ W_n1 + b_n1        (64 x 1024 x 4096)
    sgemm_splitk64<<<dim3(1024 / 64, 1, 8), 256>>>(1024, 4096, 512, netin, W_n1, part);
    reduce_bias_act<<<(64 * 1024 + 255) / 256, 256>>>(part, b_n1, n1, 1024, 0, 0);

    // 6. n2 = relu(n1 @ W_n2 + b_n2)     (64 x 4096 x 1024)
    sgemm_splitk64<<<dim3(4096 / 64, 1, 8), 256>>>(4096, 1024, 128, n1, W_n2, part);
    reduce_bias_act<<<(64 * 4096 + 255) / 256, 256>>>(part, b_n2, n2, 4096, 1, 0);

    // 7. out3 = n2 @ W_n3 + b_n3         (64 x 1024 x 4096)
    sgemm_splitk64<<<dim3(1024 / 64, 1, 8), 256>>>(1024, 4096, 512, n2, W_n3, part);
    reduce_bias_act<<<(64 * 1024 + 255) / 256, 256>>>(part, b_n3, out3, 1024, 0, 0);

    // 8. kk = out3 @ W_k + b_k           (64 x 1024 x 1024)
    sgemm_splitk64<<<dim3(1024 / 64, 1, 8), 256>>>(1024, 1024, 128, out3, W_k, part);
    reduce_bias_act<<<(64 * 1024 + 255) / 256, 256>>>(part, b_k, kk, 1024, 0, 0);

    // 9. attention 2 -> g_y
    attn2_kernel<<<dim3(NQL / 128, HH, BB), 128>>>();

    // 10. out = y @ W_o + b_o + inputs   (16384 x 1024 x 1024)
    sgemm128<<<dim3(1024 / 128, MROWS / 128), 256>>>(MROWS, 1024, 1024, y, W_o, b_o, inputs, out, 0);
}

// round 3
// speedup vs baseline: 1.8367x; 1.8367x over previous
#include <cuda_runtime.h>
#include <cuda_fp16.h>
#include <cstdint>

// ---------------- problem constants ----------------
#define BB     8
#define NQL    2048
#define ISZ    1024
#define HH     8
#define DDIM   128
#define NAA    8
#define AHD    1024
#define FHD    4096
#define MROWS  (BB*NQL)  // 16384
#define SCALE_D 0.08838834764831845f

// ---------------- static scratch ----------------
__device__ __half g_xh [(size_t)MROWS * ISZ];
__device__ __half g_xl [(size_t)MROWS * ISZ];
__device__ float  g_qkv[(size_t)MROWS * 3 * AHD];
__device__ __half g_yh [(size_t)MROWS * AHD];
__device__ __half g_yl [(size_t)MROWS * AHD];
__device__ __half g_wqh[3072 * 1024];  // W_qkv^T hi  [N,K]
__device__ __half g_wql[3072 * 1024];
__device__ __half g_woh[1024 * 1024];  // W_o^T hi
__device__ __half g_wol[1024 * 1024];
__device__ float g_att1 [BB * HH * NAA * DDIM];
__device__ float g_netin[BB * NAA * FHD];
__device__ float g_n1   [BB * NAA * AHD];
__device__ float g_n2   [BB * NAA * FHD];
__device__ float g_out3 [BB * NAA * AHD];
__device__ float g_kkb  [BB * NAA * AHD];
__device__ float g_part [8 * 64 * 4096];

// ---------------- helpers ----------------
__device__ __forceinline__ uint32_t smem_u32(const void* p) {
    uint32_t a;
    asm("{ .reg .u64 t; cvta.to.shared.u64 t, %1; cvt.u32.u64 %0, t; }" : "=r"(a) : "l"(p));
    return a;
}
__device__ __forceinline__ void cp16(uint32_t dst, const void* src) {
    asm volatile("cp.async.cg.shared.global [%0], [%1], 16;" :: "r"(dst), "l"(src) : "memory");
}
__device__ __forceinline__ void cp_commit() {
    asm volatile("cp.async.commit_group;" ::: "memory");
}
__device__ __forceinline__ void cp_wait1() {
    asm volatile("cp.async.wait_group 1;" ::: "memory");
}
__device__ __forceinline__ void split_half(float v, __half& h, __half& l) {
    h = __float2half_rn(v);
    l = __float2half_rn(v - __half2float(h));
}

#define LDM4(r, addr) \
    asm volatile("ldmatrix.sync.aligned.m8n8.x4.shared.b16 {%0,%1,%2,%3}, [%4];" \
                 : "=r"((r)[0]), "=r"((r)[1]), "=r"((r)[2]), "=r"((r)[3]) : "r"(addr))

#define MMA16816(d, a, b0, b1) \
    asm volatile("mma.sync.aligned.m16n8k16.row.col.f32.f16.f16.f32 " \
                 "{%0,%1,%2,%3}, {%4,%5,%6,%7}, {%8,%9}, {%0,%1,%2,%3};" \
                 : "+f"((d)[0]), "+f"((d)[1]), "+f"((d)[2]), "+f"((d)[3]) \
                 : "r"((a)[0]), "r"((a)[1]), "r"((a)[2]), "r"((a)[3]), "r"(b0), "r"(b1))

// ---------------- LayerNorm + fp16 hi/lo split ----------------
__global__ __launch_bounds__(256) void ln_kernel(const float* __restrict__ in,
                                                 const float* __restrict__ gam,
                                                 const float* __restrict__ bet) {
    int row = blockIdx.x;
    int tid = threadIdx.x;
    const float4 v = ((const float4*)(in + (size_t)row * ISZ))[tid];
    float s  = v.x + v.y + v.z + v.w;
    float ss = v.x*v.x + v.y*v.y + v.z*v.z + v.w*v.w;
    __shared__ float r1[32], r2[32];
    #pragma unroll
    for (int o = 16; o; o >>= 1) {
        s  += __shfl_xor_sync(0xffffffffu, s,  o);
        ss += __shfl_xor_sync(0xffffffffu, ss, o);
    }
    if ((tid & 31) == 0) { r1[tid >> 5] = s; r2[tid >> 5] = ss; }
    __syncthreads();
    if (tid < 32) {
        float a = (tid < 8) ? r1[tid] : 0.f;
        float b = (tid < 8) ? r2[tid] : 0.f;
        #pragma unroll
        for (int o = 4; o; o >>= 1) {
            a += __shfl_xor_sync(0xffffffffu, a, o);
            b += __shfl_xor_sync(0xffffffffu, b, o);
        }
        if (tid == 0) { r1[0] = a; r2[0] = b; }
    }
    __syncthreads();
    float mean = r1[0] * (1.0f / ISZ);
    float var  = r2[0] * (1.0f / ISZ) - mean * mean;
    float rstd = rsqrtf(var + 1e-6f);
    const float4 g4 = ((const float4*)gam)[tid];
    const float4 b4 = ((const float4*)bet)[tid];
    float o0 = (v.x - mean) * rstd * g4.x + b4.x;
    float o1 = (v.y - mean) * rstd * g4.y + b4.y;
    float o2 = (v.z - mean) * rstd * g4.z + b4.z;
    float o3 = (v.w - mean) * rstd * g4.w + b4.w;
    __half h0,h1,h2,h3,l0,l1,l2,l3;
    split_half(o0,h0,l0); split_half(o1,h1,l1); split_half(o2,h2,l2); split_half(o3,h3,l3);
    __half2* ph = (__half2*)(g_xh + (size_t)row * ISZ);
    __half2* pl = (__half2*)(g_xl + (size_t)row * ISZ);
    ph[tid*2]   = __halves2half2(h0,h1);
    ph[tid*2+1] = __halves2half2(h2,h3);
    pl[tid*2]   = __halves2half2(l0,l1);
    pl[tid*2+1] = __halves2half2(l2,l3);
}

// ---------------- weight transpose + split: W[K][N] -> Wh/Wl [N][K] ----------------
__global__ __launch_bounds__(256) void convw_kernel(const float* __restrict__ W,
                                                    __half* __restrict__ Wh,
                                                    __half* __restrict__ Wl,
                                                    int K, int N) {
    __shared__ float t[32][33];
    int n0 = blockIdx.x * 32, k0 = blockIdx.y * 32;
    int tx = threadIdx.x & 31, ty = threadIdx.x >> 5;
    #pragma unroll
    for (int i = 0; i < 4; i++)
        t[ty + i*8][tx] = W[(size_t)(k0 + ty + i*8) * N + n0 + tx];
    __syncthreads();
    #pragma unroll
    for (int i = 0; i < 4; i++) {
        int nn = ty + i*8;
        float v = t[tx][nn];
        __half h, l;
        split_half(v, h, l);
        Wh[(size_t)(n0 + nn) * K + k0 + tx] = h;
        Wl[(size_t)(n0 + nn) * K + k0 + tx] = l;
    }
}

// ---------------- HMMA split-precision GEMM ----------------
// C[M,N] = (Ah+Al)[M,K] @ (Bh+Bl)[N,K]^T (+bias +resid), fp32 out.
// CTA 128x128, 8 warps as 2(M)x4(N), warp tile 64x32, K-chunk 32, 3-stage cp.async.
#define GSTAGE 40960   // 4 matrices x 128 rows x 40 halfs x 2B
#define MAT_B  10240
__global__ __launch_bounds__(256, 1)
void gemm_hmma(int N, int K,
               const __half* __restrict__ Ah, const __half* __restrict__ Al,
               const __half* __restrict__ Bh, const __half* __restrict__ Bl,
               const float* __restrict__ bias, const float* __restrict__ resid,
               float* __restrict__ C) {
    extern __shared__ __align__(16) char dsm[];
    const int tid  = threadIdx.x;
    const int wid  = tid >> 5;
    const int lane = tid & 31;
    const int wm   = wid >> 2;        // 0..1
    const int wn   = wid & 3;         // 0..3
    const int m0   = blockIdx.y * 128;
    const int n0   = blockIdx.x * 128;
    const uint32_t dynb = smem_u32(dsm);

    float acc[4][4][4];
    #pragma unroll
    for (int i = 0; i < 4; i++)
        #pragma unroll
        for (int j = 0; j < 4; j++)
            #pragma unroll
            for (int q = 0; q < 4; q++) acc[i][j][q] = 0.f;

    const __half* srcs[4];
    srcs[0] = Ah + (size_t)m0 * K;
    srcs[1] = Al + (size_t)m0 * K;
    srcs[2] = Bh + (size_t)n0 * K;
    srcs[3] = Bl + (size_t)n0 * K;

    const int NCH = K >> 5;   // chunks of 32

    auto load_chunk = [&](int chunk, int s) {
        uint32_t base = dynb + s * GSTAGE;
        int k0 = chunk * 32;
        #pragma unroll
        for (int i = 0; i < 8; i++) {
            int mat = i >> 1;
            int row = ((i & 1) << 6) + (tid >> 2);
            int c4  = tid & 3;
            uint32_t dst = base + mat * MAT_B + row * 80 + c4 * 16;
            cp16(dst, srcs[mat] + (size_t)row * K + k0 + c4 * 8);
        }
    };

    load_chunk(0, 0); cp_commit();
    load_chunk(1, 1); cp_commit();

    // ldmatrix source addresses (byte offsets within a matrix)
    const int arow = wm * 64 + (lane & 15);
    const int acol = (lane >> 4) * 8;                    // 0 or 8
    const int brow = wn * 32 + (lane & 7) + ((lane >> 4) << 3);
    const int bcol = ((lane >> 3) & 1) * 8;

    for (int c = 0; c < NCH; c++) {
        cp_wait1();
        __syncthreads();
        if (c + 2 < NCH) load_chunk(c + 2, (c + 2) % 3);
        cp_commit();

        uint32_t base = dynb + (c % 3) * GSTAGE;
        #pragma unroll
        for (int step = 0; step < 2; step++) {
            int kb = step * 16;
            uint32_t ah4[4][4], al4[4][4], bh4[2][4], bl4[2][4];
            #pragma unroll
            for (int mt = 0; mt < 4; mt++) {
                uint32_t off = (uint32_t)((arow + mt * 16) * 80 + (kb + acol) * 2);
                LDM4(ah4[mt], base + off);
                LDM4(al4[mt], base + MAT_B + off);
            }
            #pragma unroll
            for (int ng = 0; ng < 2; ng++) {
                uint32_t off = (uint32_t)((brow + ng * 16) * 80 + (kb + bcol) * 2);
                LDM4(bh4[ng], base + 2 * MAT_B + off);
                LDM4(bl4[ng], base + 3 * MAT_B + off);
            }
            #pragma unroll
            for (int mt = 0; mt < 4; mt++) {
                #pragma unroll
                for (int nt = 0; nt < 4; nt++) {
                    int ng = nt >> 1, hb = (nt & 1) * 2;
                    MMA16816(acc[mt][nt], ah4[mt], bh4[ng][hb], bh4[ng][hb + 1]);
                    MMA16816(acc[mt][nt], ah4[mt], bl4[ng][hb], bl4[ng][hb + 1]);
                    MMA16816(acc[mt][nt], al4[mt], bh4[ng][hb], bh4[ng][hb + 1]);
                }
            }
        }
        __syncthreads();
    }

    // ---- epilogue: direct float2 stores with bias/resid fusion ----
    #pragma unroll
    for (int mt = 0; mt < 4; mt++) {
        #pragma unroll
        for (int nt = 0; nt < 4; nt++) {
            int row = m0 + wm * 64 + mt * 16 + (lane >> 2);
            int col = n0 + wn * 32 + nt * 8 + (lane & 3) * 2;
            float b0 = bias[col], b1 = bias[col + 1];
            #pragma unroll
            for (int hh = 0; hh < 2; hh++) {
                int r = row + hh * 8;
                float o0 = acc[mt][nt][hh * 2 + 0] + b0;
                float o1 = acc[mt][nt][hh * 2 + 1] + b1;
                if (resid) {
                    const float2 rv = *(const float2*)(resid + (size_t)r * N + col);
                    o0 += rv.x; o1 += rv.y;
                }
                *(float2*)(C + (size_t)r * N + col) = make_float2(o0, o1);
            }
        }
    }
}

// ---------------- split-K SGEMM for skinny M=64 middle GEMMs ----------------
__global__ __launch_bounds__(256)
void sgemm_splitk64(int N, int K, int kc,
                    const float* __restrict__ A, const float* __restrict__ B,
                    float* __restrict__ part) {
    __shared__ __align__(16) float As[8][68];
    __shared__ __align__(16) float Bs[8][64];
    const int tid = threadIdx.x;
    const int bx = blockIdx.x, z = blockIdx.z;
    const int tx = tid & 15, ty = tid >> 4;
    const int aRow = tid >> 2;
    const int aK   = (tid & 3) * 2;
    const int bRow = tid >> 5;
    const int bCol = (tid & 31) * 2;
    const int kb = z * kc;
    float acc[4][4];
    #pragma unroll
    for (int i = 0; i < 4; i++)
        #pragma unroll
        for (int j = 0; j < 4; j++) acc[i][j] = 0.f;
    for (int k0 = kb; k0 < kb + kc; k0 += 8) {
        float2 a2 = *(const float2*)(A + (size_t)aRow * K + k0 + aK);
        float2 b2 = *(const float2*)(B + (size_t)(k0 + bRow) * N + bx * 64 + bCol);
        __syncthreads();
        As[aK][aRow] = a2.x; As[aK + 1][aRow] = a2.y;
        Bs[bRow][bCol] = b2.x; Bs[bRow][bCol + 1] = b2.y;
        __syncthreads();
        #pragma unroll
        for (int kk = 0; kk < 8; kk++) {
            float ra[4], rb[4];
            #pragma unroll
            for (int i = 0; i < 4; i++) ra[i] = As[kk][ty * 4 + i];
            #pragma unroll
            for (int j = 0; j < 4; j++) rb[j] = Bs[kk][tx * 4 + j];
            #pragma unroll
            for (int i = 0; i < 4; i++)
                #pragma unroll
                for (int j = 0; j < 4; j++) acc[i][j] += ra[i] * rb[j];
        }
    }
    #pragma unroll
    for (int i = 0; i < 4; i++) {
        float* p = part + (size_t)z * 64 * N + (size_t)(ty * 4 + i) * N + bx * 64 + tx * 4;
        *(float4*)p = make_float4(acc[i][0], acc[i][1], acc[i][2], acc[i][3]);
    }
}

__global__ __launch_bounds__(256)
void reduce_bias_act(const float* __restrict__ part, const float* __restrict__ bias,
                     float* __restrict__ out, int N, int act, int permute) {
    int idx = blockIdx.x * 256 + threadIdx.x;
    int total = 64 * N;
    if (idx >= total) return;
    int m = idx / N, n = idx - m * N;
    float s = 0.f;
    #pragma unroll
    for (int z = 0; z < 8; z++) s += part[(size_t)z * total + idx];
    s += bias[n];
    if (act) s = fmaxf(s, 0.f);
    if (permute) {
        int b = m >> 3, h = m & 7;
        int na = n >> 9, j = n & 511;
        out[((size_t)(b * 8 + na)) * 4096 + h * 512 + j] = s;
    } else {
        out[idx] = s;
    }
}

// ---------------- attention 1: one block per (b,h), all 8 anchors ----------------
__global__ __launch_bounds__(256) void attn1_kernel(const float* __restrict__ q_anchor) {
    extern __shared__ float a1s[];
    float* probs   = a1s;                   // [8][2048]
    float* qs      = a1s + 8 * 2048;        // [8][128]
    float* halfbuf = qs + 8 * 128;          // [8][128]
    float* red     = halfbuf + 8 * 128;     // [8 warps][8]
    float* Mv      = red + 64;              // [8]
    float* invS    = Mv + 8;                // [8]
    const int h = blockIdx.x & 7;
    const int b = blockIdx.x >> 3;
    const int tid = threadIdx.x;
    const int warp = tid >> 5, lane = tid & 31;

    for (int i = tid; i < 1024; i += 256) qs[i] = q_anchor[h * 1024 + i];
    __syncthreads();

    float lmax[8];
    #pragma unroll
    for (int a = 0; a < 8; a++) lmax[a] = -1e30f;
    #pragma unroll
    for (int i = 0; i < 8; i++) {
        int n = tid + i * 256;
        const float4* kr = (const float4*)(g_qkv + (((size_t)(b * NQL + n)) * 3 + 1) * AHD + h * DDIM);
        float lg[8];
        #pragma unroll
        for (int a = 0; a < 8; a++) lg[a] = 0.f;
        #pragma unroll
        for (int j = 0; j < 32; j++) {
            float4 kv = kr[j];
            #pragma unroll
            for (int a = 0; a < 8; a++) {
                float4 qv = ((const float4*)(qs + a * 128))[j];
                lg[a] += kv.x*qv.x + kv.y*qv.y + kv.z*qv.z + kv.w*qv.w;
            }
        }
        #pragma unroll
        for (int a = 0; a < 8; a++) {
            float v = lg[a] * SCALE_D;
            probs[a * 2048 + n] = v;
            lmax[a] = fmaxf(lmax[a], v);
        }
    }
    #pragma unroll
    for (int a = 0; a < 8; a++) {
        #pragma unroll
        for (int o = 16; o; o >>= 1) lmax[a] = fmaxf(lmax[a], __shfl_xor_sync(0xffffffffu, lmax[a], o));
    }
    if (lane == 0)
        #pragma unroll
        for (int a = 0; a < 8; a++) red[warp * 8 + a] = lmax[a];
    __syncthreads();
    if (tid < 8) {
        float m = -1e30f;
        #pragma unroll
        for (int w = 0; w < 8; w++) m = fmaxf(m, red[w * 8 + tid]);
        Mv[tid] = m;
    }
    __syncthreads();

    float lsum[8];
    #pragma unroll
    for (int a = 0; a < 8; a++) lsum[a] = 0.f;
    #pragma unroll
    for (int i = 0; i < 8; i++) {
        int n = tid + i * 256;
        #pragma unroll
        for (int a = 0; a < 8; a++) {
            float e = __expf(probs[a * 2048 + n] - Mv[a]);
            probs[a * 2048 + n] = e;
            lsum[a] += e;
        }
    }
    #pragma unroll
    for (int a = 0; a < 8; a++) {
        #pragma unroll
        for (int o = 16; o; o >>= 1) lsum[a] += __shfl_xor_sync(0xffffffffu, lsum[a], o);
    }
    __syncthreads();
    if (lane == 0)
        #pragma unroll
        for (int a = 0; a < 8; a++) red[warp * 8 + a] = lsum[a];
    __syncthreads();
    if (tid < 8) {
        float s = 0.f;
        #pragma unroll
        for (int w = 0; w < 8; w++) s += red[w * 8 + tid];
        invS[tid] = 1.0f / s;
    }
    __syncthreads();

    const int d = tid & 127, hf = tid >> 7;
    float acc[8];
    #pragma unroll
    for (int a = 0; a < 8; a++) acc[a] = 0.f;
    const int nbase = hf * 1024;
    for (int n4 = 0; n4 < 256; n4++) {
        int n = nbase + n4 * 4;
        float4 pv[8];
        #pragma unroll
        for (int a = 0; a < 8; a++) pv[a] = *(const float4*)(probs + a * 2048 + n);
        #pragma unroll
        for (int t = 0; t < 4; t++) {
            float v = g_qkv[(((size_t)(b * NQL + n + t)) * 3 + 2) * AHD + h * DDIM + d];
            #pragma unroll
            for (int a = 0; a < 8; a++) {
                float p = (t == 0) ? pv[a].x : (t == 1) ? pv[a].y : (t == 2) ? pv[a].z : pv[a].w;
                acc[a] += p * v;
            }
        }
    }
    if (hf)
        #pragma unroll
        for (int a = 0; a < 8; a++) halfbuf[a * 128 + d] = acc[a];
    __syncthreads();
    if (!hf)
        #pragma unroll
        for (int a = 0; a < 8; a++)
            g_att1[(((size_t)(b * 8 + h)) * 8 + a) * 128 + d] = (acc[a] + halfbuf[a * 128 + d]) * invS[a];
}

// ---------------- attention 2: writes y split into fp16 hi/lo ----------------
__global__ __launch_bounds__(128) void attn2_kernel() {
    const int nc = blockIdx.x;
    const int h  = blockIdx.y;
    const int b  = blockIdx.z;
    const int tid = threadIdx.x;
    __shared__ __align__(16) float kks[8][128];
    __shared__ __align__(16) float ovs[8][128];
    __shared__ float ps[128][9];
    #pragma unroll
    for (int r = 0; r < 8; r++) {
        kks[r][tid] = g_kkb [((size_t)(b * 8 + r)) * AHD + h * 128 + tid];
        ovs[r][tid] = g_out3[((size_t)(b * 8 + r)) * AHD + h * 128 + tid];
    }
    __syncthreads();
    const int n = nc * 128 + tid;
    const float4* qr = (const float4*)(g_qkv + ((size_t)(b * NQL + n)) * 3 * AHD + h * 128);
    float lg[8];
    #pragma unroll
    for (int aa = 0; aa < 8; aa++) lg[aa] = 0.f;
    #pragma unroll
    for (int j = 0; j < 32; j++) {
        float4 qv = qr[j];
        #pragma unroll
        for (int aa = 0; aa < 8; aa++) {
            float4 kv = ((const float4*)kks[aa])[j];
            lg[aa] += qv.x*kv.x + qv.y*kv.y + qv.z*kv.z + qv.w*kv.w;
        }
    }
    float m = -1e30f;
    #pragma unroll
    for (int aa = 0; aa < 8; aa++) { lg[aa] *= SCALE_D; m = fmaxf(m, lg[aa]); }
    float s = 0.f;
    #pragma unroll
    for (int aa = 0; aa < 8; aa++) { lg[aa] = __expf(lg[aa] - m); s += lg[aa]; }
    float inv = 1.0f / s;
    #pragma unroll
    for (int aa = 0; aa < 8; aa++) ps[tid][aa] = lg[aa] * inv;
    __syncthreads();
    for (int i = 0; i < 128; i++) {
        float acc = 0.f;
        #pragma unroll
        for (int aa = 0; aa < 8; aa++) acc += ps[i][aa] * ovs[aa][tid];
        size_t idx = ((size_t)(b * NQL) + nc * 128 + i) * AHD + h * 128 + tid;
        __half hh, ll;
        split_half(acc, hh, ll);
        g_yh[idx] = hh;
        g_yl[idx] = ll;
    }
}

// ---------------- host orchestration ----------------
extern "C" void kernel_launch(void* const* d_in, const int* in_sizes, int n_in,
                              void* d_out, int out_size) {
    (void)in_sizes; (void)n_in; (void)out_size;
    const float* inputs   = (const float*)d_in[0];
    const float* ln_g     = (const float*)d_in[1];
    const float* ln_b     = (const float*)d_in[2];
    const float* q_anchor = (const float*)d_in[3];
    const float* W_qkv    = (const float*)d_in[4];
    const float* b_qkv    = (const float*)d_in[5];
    const float* W_an     = (const float*)d_in[6];
    const float* b_an     = (const float*)d_in[7];
    const float* W_n1     = (const float*)d_in[8];
    const float* b_n1     = (const float*)d_in[9];
    const float* W_n2     = (const float*)d_in[10];
    const float* b_n2     = (const float*)d_in[11];
    const float* W_n3     = (const float*)d_in[12];
    const float* b_n3     = (const float*)d_in[13];
    const float* W_k      = (const float*)d_in[14];
    const float* b_k      = (const float*)d_in[15];
    const float* W_o      = (const float*)d_in[16];
    const float* b_o      = (const float*)d_in[17];
    float* out = (float*)d_out;

    float *qkv, *att1, *netin, *n1, *n2, *out3, *kk, *part;
    __half *xh, *xl, *yh, *yl, *wqh, *wql, *woh, *wol;
    cudaGetSymbolAddress((void**)&qkv,  g_qkv);
    cudaGetSymbolAddress((void**)&att1, g_att1);
    cudaGetSymbolAddress((void**)&netin,g_netin);
    cudaGetSymbolAddress((void**)&n1,   g_n1);
    cudaGetSymbolAddress((void**)&n2,   g_n2);
    cudaGetSymbolAddress((void**)&out3, g_out3);
    cudaGetSymbolAddress((void**)&kk,   g_kkb);
    cudaGetSymbolAddress((void**)&part, g_part);
    cudaGetSymbolAddress((void**)&xh,   g_xh);
    cudaGetSymbolAddress((void**)&xl,   g_xl);
    cudaGetSymbolAddress((void**)&yh,   g_yh);
    cudaGetSymbolAddress((void**)&yl,   g_yl);
    cudaGetSymbolAddress((void**)&wqh,  g_wqh);
    cudaGetSymbolAddress((void**)&wql,  g_wql);
    cudaGetSymbolAddress((void**)&woh,  g_woh);
    cudaGetSymbolAddress((void**)&wol,  g_wol);

    static int attr_done = 0;
    if (!attr_done) {
        cudaFuncSetAttribute(gemm_hmma, cudaFuncAttributeMaxDynamicSharedMemorySize, 3 * GSTAGE);
        cudaFuncSetAttribute(attn1_kernel, cudaFuncAttributeMaxDynamicSharedMemorySize, 74112);
        attr_done = 1;
    }

    // weight conversion (transpose + hi/lo split)
    convw_kernel<<<dim3(3072/32, 1024/32), 256>>>(W_qkv, wqh, wql, 1024, 3072);
    convw_kernel<<<dim3(1024/32, 1024/32), 256>>>(W_o,   woh, wol, 1024, 1024);

    // LN (+ split into xh/xl)
    ln_kernel<<<MROWS, 256>>>(inputs, ln_g, ln_b);

    // qkv = x @ W_qkv + b_qkv     (HMMA, 16384 x 3072 x 1024)
    gemm_hmma<<<dim3(3072/128, MROWS/128), 256, 3*GSTAGE>>>(
        3072, 1024, xh, xl, wqh, wql, b_qkv, nullptr, qkv);

    // attention 1
    attn1_kernel<<<BB * HH, 256, 74112>>>(q_anchor);

    // middle MLP chain (fp32 split-K)
    sgemm_splitk64<<<dim3(4096/64, 1, 8), 256>>>(4096, 1024, 128, att1, W_an, part);
    reduce_bias_act<<<(64*4096 + 255)/256, 256>>>(part, b_an, netin, 4096, 1, 1);
    sgemm_splitk64<<<dim3(1024/64, 1, 8), 256>>>(1024, 4096, 512, netin, W_n1, part);
    reduce_bias_act<<<(64*1024 + 255)/256, 256>>>(part, b_n1, n1, 1024, 0, 0);
    sgemm_splitk64<<<dim3(4096/64, 1, 8), 256>>>(4096, 1024, 128, n1, W_n2, part);
    reduce_bias_act<<<(64*4096 + 255)/256, 256>>>(part, b_n2, n2, 4096, 1, 0);
    sgemm_splitk64<<<dim3(1024/64, 1, 8), 256>>>(1024, 4096, 512, n2, W_n3, part);
    reduce_bias_act<<<(64*1024 + 255)/256, 256>>>(part, b_n3, out3, 1024, 0, 0);
    sgemm_splitk64<<<dim3(1024/64, 1, 8), 256>>>(1024, 1024, 128, out3, W_k, part);
    reduce_bias_act<<<(64*1024 + 255)/256, 256>>>(part, b_k, kk, 1024, 0, 0);

    // attention 2 (+ split y into yh/yl)
    attn2_kernel<<<dim3(NQL/128, HH, BB), 128>>>();

    // out = y @ W_o + b_o + inputs   (HMMA, 16384 x 1024 x 1024)
    gemm_hmma<<<dim3(1024/128, MROWS/128), 256, 3*GSTAGE>>>(
        1024, 1024, yh, yl, woh, wol, b_o, inputs, out);
}

// round 4
// speedup vs baseline: 3.4297x; 1.8673x over previous
#include <cuda_runtime.h>
#include <cuda_fp16.h>
#include <cstdint>

// ---------------- problem constants ----------------
#define BB     8
#define NQL    2048
#define ISZ    1024
#define HH     8
#define DDIM   128
#define NAA    8
#define AHD    1024
#define FHD    4096
#define MROWS  (BB*NQL)  // 16384
#define SCALE_D 0.08838834764831845f

// ---------------- static scratch ----------------
__device__ __half g_xh [(size_t)MROWS * ISZ];
__device__ float  g_qkv[(size_t)MROWS * 3 * AHD];
__device__ __half g_yh [(size_t)MROWS * AHD];
__device__ __half g_wqh[3072 * 1024];  // W_qkv^T  [N,K]
__device__ __half g_woh[1024 * 1024];  // W_o^T
__device__ float g_att1 [BB * HH * NAA * DDIM];
__device__ float g_netin[BB * NAA * FHD];
__device__ float g_n1   [BB * NAA * AHD];
__device__ float g_n2   [BB * NAA * FHD];
__device__ float g_out3 [BB * NAA * AHD];
__device__ float g_kkb  [BB * NAA * AHD];
__device__ float g_part [8 * 64 * 4096];

// ---------------- helpers ----------------
__device__ __forceinline__ uint32_t smem_u32(const void* p) {
    uint32_t a;
    asm("{ .reg .u64 t; cvta.to.shared.u64 t, %1; cvt.u32.u64 %0, t; }" : "=r"(a) : "l"(p));
    return a;
}
__device__ __forceinline__ void cp16(uint32_t dst, const void* src) {
    asm volatile("cp.async.cg.shared.global [%0], [%1], 16;" :: "r"(dst), "l"(src) : "memory");
}
__device__ __forceinline__ void cp_commit() {
    asm volatile("cp.async.commit_group;" ::: "memory");
}
__device__ __forceinline__ void cp_wait1() {
    asm volatile("cp.async.wait_group 1;" ::: "memory");
}

#define LDM4(r, addr) \
    asm volatile("ldmatrix.sync.aligned.m8n8.x4.shared.b16 {%0,%1,%2,%3}, [%4];" \
                 : "=r"((r)[0]), "=r"((r)[1]), "=r"((r)[2]), "=r"((r)[3]) : "r"(addr))

#define MMA16816(d, a, b0, b1) \
    asm volatile("mma.sync.aligned.m16n8k16.row.col.f32.f16.f16.f32 " \
                 "{%0,%1,%2,%3}, {%4,%5,%6,%7}, {%8,%9}, {%0,%1,%2,%3};" \
                 : "+f"((d)[0]), "+f"((d)[1]), "+f"((d)[2]), "+f"((d)[3]) \
                 : "r"((a)[0]), "r"((a)[1]), "r"((a)[2]), "r"((a)[3]), "r"(b0), "r"(b1))

// ---------------- LayerNorm -> fp16 ----------------
__global__ __launch_bounds__(256) void ln_kernel(const float* __restrict__ in,
                                                 const float* __restrict__ gam,
                                                 const float* __restrict__ bet) {
    int row = blockIdx.x;
    int tid = threadIdx.x;
    const float4 v = ((const float4*)(in + (size_t)row * ISZ))[tid];
    float s  = v.x + v.y + v.z + v.w;
    float ss = v.x*v.x + v.y*v.y + v.z*v.z + v.w*v.w;
    __shared__ float r1[32], r2[32];
    #pragma unroll
    for (int o = 16; o; o >>= 1) {
        s  += __shfl_xor_sync(0xffffffffu, s,  o);
        ss += __shfl_xor_sync(0xffffffffu, ss, o);
    }
    if ((tid & 31) == 0) { r1[tid >> 5] = s; r2[tid >> 5] = ss; }
    __syncthreads();
    if (tid < 32) {
        float a = (tid < 8) ? r1[tid] : 0.f;
        float b = (tid < 8) ? r2[tid] : 0.f;
        #pragma unroll
        for (int o = 4; o; o >>= 1) {
            a += __shfl_xor_sync(0xffffffffu, a, o);
            b += __shfl_xor_sync(0xffffffffu, b, o);
        }
        if (tid == 0) { r1[0] = a; r2[0] = b; }
    }
    __syncthreads();
    float mean = r1[0] * (1.0f / ISZ);
    float var  = r2[0] * (1.0f / ISZ) - mean * mean;
    float rstd = rsqrtf(var + 1e-6f);
    const float4 g4 = ((const float4*)gam)[tid];
    const float4 b4 = ((const float4*)bet)[tid];
    float o0 = (v.x - mean) * rstd * g4.x + b4.x;
    float o1 = (v.y - mean) * rstd * g4.y + b4.y;
    float o2 = (v.z - mean) * rstd * g4.z + b4.z;
    float o3 = (v.w - mean) * rstd * g4.w + b4.w;
    __half2* ph = (__half2*)(g_xh + (size_t)row * ISZ);
    ph[tid*2]   = __halves2half2(__float2half_rn(o0), __float2half_rn(o1));
    ph[tid*2+1] = __halves2half2(__float2half_rn(o2), __float2half_rn(o3));
}

// ---------------- weight transpose: W[K][N] -> Wh [N][K] fp16 ----------------
__global__ __launch_bounds__(256) void convw_kernel(const float* __restrict__ W,
                                                    __half* __restrict__ Wh,
                                                    int K, int N) {
    __shared__ float t[32][33];
    int n0 = blockIdx.x * 32, k0 = blockIdx.y * 32;
    int tx = threadIdx.x & 31, ty = threadIdx.x >> 5;
    #pragma unroll
    for (int i = 0; i < 4; i++)
        t[ty + i*8][tx] = W[(size_t)(k0 + ty + i*8) * N + n0 + tx];
    __syncthreads();
    #pragma unroll
    for (int i = 0; i < 4; i++) {
        int nn = ty + i*8;
        Wh[(size_t)(n0 + nn) * K + k0 + tx] = __float2half_rn(t[tx][nn]);
    }
}

// ---------------- HMMA fp16 GEMM ----------------
// C[M,N] = A[M,K] @ B[N,K]^T (+bias +resid), fp32 out.
// CTA 128x128, 8 warps as 2(M)x4(N), warp tile 64x32, K-chunk 32, 3-stage cp.async.
#define GSTAGE 20480   // 2 matrices x 128 rows x 40 halfs x 2B
#define MAT_B  10240
__global__ __launch_bounds__(256, 2)
void gemm_hmma(int N, int K,
               const __half* __restrict__ A,
               const __half* __restrict__ B,
               const float* __restrict__ bias, const float* __restrict__ resid,
               float* __restrict__ C) {
    extern __shared__ __align__(16) char dsm[];
    const int tid  = threadIdx.x;
    const int wid  = tid >> 5;
    const int lane = tid & 31;
    const int wm   = wid >> 2;        // 0..1
    const int wn   = wid & 3;         // 0..3
    const int m0   = blockIdx.y * 128;
    const int n0   = blockIdx.x * 128;
    const uint32_t dynb = smem_u32(dsm);

    float acc[4][4][4];
    #pragma unroll
    for (int i = 0; i < 4; i++)
        #pragma unroll
        for (int j = 0; j < 4; j++)
            #pragma unroll
            for (int q = 0; q < 4; q++) acc[i][j][q] = 0.f;

    const __half* srcA = A + (size_t)m0 * K;
    const __half* srcB = B + (size_t)n0 * K;

    const int NCH = K >> 5;   // chunks of 32

    auto load_chunk = [&](int chunk, int s) {
        uint32_t base = dynb + s * GSTAGE;
        int k0 = chunk * 32;
        int row = tid >> 2;
        int c4  = tid & 3;
        uint32_t off = row * 80 + c4 * 16;
        cp16(base + off,                 srcA + (size_t)row * K + k0 + c4 * 8);
        cp16(base + 5120 + off,          srcA + (size_t)(row + 64) * K + k0 + c4 * 8);
        cp16(base + MAT_B + off,         srcB + (size_t)row * K + k0 + c4 * 8);
        cp16(base + MAT_B + 5120 + off,  srcB + (size_t)(row + 64) * K + k0 + c4 * 8);
    };

    load_chunk(0, 0); cp_commit();
    load_chunk(1, 1); cp_commit();

    const int arow = wm * 64 + (lane & 15);
    const int acol = (lane >> 4) * 8;
    const int brow = wn * 32 + (lane & 7) + ((lane >> 4) << 3);
    const int bcol = ((lane >> 3) & 1) * 8;

    for (int c = 0; c < NCH; c++) {
        cp_wait1();
        __syncthreads();
        if (c + 2 < NCH) load_chunk(c + 2, (c + 2) % 3);
        cp_commit();

        uint32_t base = dynb + (c % 3) * GSTAGE;
        #pragma unroll
        for (int step = 0; step < 2; step++) {
            int kb = step * 16;
            uint32_t ah4[4][4], bh4[2][4];
            #pragma unroll
            for (int mt = 0; mt < 4; mt++) {
                uint32_t off = (uint32_t)((arow + mt * 16) * 80 + (kb + acol) * 2);
                LDM4(ah4[mt], base + off);
            }
            #pragma unroll
            for (int ng = 0; ng < 2; ng++) {
                uint32_t off = (uint32_t)((brow + ng * 16) * 80 + (kb + bcol) * 2);
                LDM4(bh4[ng], base + MAT_B + off);
            }
            #pragma unroll
            for (int mt = 0; mt < 4; mt++) {
                #pragma unroll
                for (int nt = 0; nt < 4; nt++) {
                    int ng = nt >> 1, hb = (nt & 1) * 2;
                    MMA16816(acc[mt][nt], ah4[mt], bh4[ng][hb], bh4[ng][hb + 1]);
                }
            }
        }
        __syncthreads();
    }

    // ---- epilogue ----
    #pragma unroll
    for (int mt = 0; mt < 4; mt++) {
        #pragma unroll
        for (int nt = 0; nt < 4; nt++) {
            int row = m0 + wm * 64 + mt * 16 + (lane >> 2);
            int col = n0 + wn * 32 + nt * 8 + (lane & 3) * 2;
            float b0 = bias[col], b1 = bias[col + 1];
            #pragma unroll
            for (int hh = 0; hh < 2; hh++) {
                int r = row + hh * 8;
                float o0 = acc[mt][nt][hh * 2 + 0] + b0;
                float o1 = acc[mt][nt][hh * 2 + 1] + b1;
                if (resid) {
                    const float2 rv = *(const float2*)(resid + (size_t)r * N + col);
                    o0 += rv.x; o1 += rv.y;
                }
                *(float2*)(C + (size_t)r * N + col) = make_float2(o0, o1);
            }
        }
    }
}

// ---------------- split-K SGEMM for skinny M=64 middle GEMMs ----------------
__global__ __launch_bounds__(256)
void sgemm_splitk64(int N, int K, int kc,
                    const float* __restrict__ A, const float* __restrict__ B,
                    float* __restrict__ part) {
    __shared__ __align__(16) float As[8][68];
    __shared__ __align__(16) float Bs[8][64];
    const int tid = threadIdx.x;
    const int bx = blockIdx.x, z = blockIdx.z;
    const int tx = tid & 15, ty = tid >> 4;
    const int aRow = tid >> 2;
    const int aK   = (tid & 3) * 2;
    const int bRow = tid >> 5;
    const int bCol = (tid & 31) * 2;
    const int kb = z * kc;
    float acc[4][4];
    #pragma unroll
    for (int i = 0; i < 4; i++)
        #pragma unroll
        for (int j = 0; j < 4; j++) acc[i][j] = 0.f;
    for (int k0 = kb; k0 < kb + kc; k0 += 8) {
        float2 a2 = *(const float2*)(A + (size_t)aRow * K + k0 + aK);
        float2 b2 = *(const float2*)(B + (size_t)(k0 + bRow) * N + bx * 64 + bCol);
        __syncthreads();
        As[aK][aRow] = a2.x; As[aK + 1][aRow] = a2.y;
        Bs[bRow][bCol] = b2.x; Bs[bRow][bCol + 1] = b2.y;
        __syncthreads();
        #pragma unroll
        for (int kk = 0; kk < 8; kk++) {
            float ra[4], rb[4];
            #pragma unroll
            for (int i = 0; i < 4; i++) ra[i] = As[kk][ty * 4 + i];
            #pragma unroll
            for (int j = 0; j < 4; j++) rb[j] = Bs[kk][tx * 4 + j];
            #pragma unroll
            for (int i = 0; i < 4; i++)
                #pragma unroll
                for (int j = 0; j < 4; j++) acc[i][j] += ra[i] * rb[j];
        }
    }
    #pragma unroll
    for (int i = 0; i < 4; i++) {
        float* p = part + (size_t)z * 64 * N + (size_t)(ty * 4 + i) * N + bx * 64 + tx * 4;
        *(float4*)p = make_float4(acc[i][0], acc[i][1], acc[i][2], acc[i][3]);
    }
}

__global__ __launch_bounds__(256)
void reduce_bias_act(const float* __restrict__ part, const float* __restrict__ bias,
                     float* __restrict__ out, int N, int act, int permute) {
    int idx = blockIdx.x * 256 + threadIdx.x;
    int total = 64 * N;
    if (idx >= total) return;
    int m = idx / N, n = idx - m * N;
    float s = 0.f;
    #pragma unroll
    for (int z = 0; z < 8; z++) s += part[(size_t)z * total + idx];
    s += bias[n];
    if (act) s = fmaxf(s, 0.f);
    if (permute) {
        int b = m >> 3, h = m & 7;
        int na = n >> 9, j = n & 511;
        out[((size_t)(b * 8 + na)) * 4096 + h * 512 + j] = s;
    } else {
        out[idx] = s;
    }
}

// ---------------- attention 1: one block per (b,h), all 8 anchors ----------------
__global__ __launch_bounds__(256) void attn1_kernel(const float* __restrict__ q_anchor) {
    extern __shared__ float a1s[];
    float* probs   = a1s;                   // [8][2048]
    float* qs      = a1s + 8 * 2048;        // [8][128]
    float* halfbuf = qs + 8 * 128;          // [8][128]
    float* red     = halfbuf + 8 * 128;     // [8 warps][8]
    float* Mv      = red + 64;              // [8]
    float* invS    = Mv + 8;                // [8]
    const int h = blockIdx.x & 7;
    const int b = blockIdx.x >> 3;
    const int tid = threadIdx.x;
    const int warp = tid >> 5, lane = tid & 31;

    for (int i = tid; i < 1024; i += 256) qs[i] = q_anchor[h * 1024 + i];
    __syncthreads();

    float lmax[8];
    #pragma unroll
    for (int a = 0; a < 8; a++) lmax[a] = -1e30f;
    #pragma unroll
    for (int i = 0; i < 8; i++) {
        int n = tid + i * 256;
        const float4* kr = (const float4*)(g_qkv + (((size_t)(b * NQL + n)) * 3 + 1) * AHD + h * DDIM);
        float lg[8];
        #pragma unroll
        for (int a = 0; a < 8; a++) lg[a] = 0.f;
        #pragma unroll
        for (int j = 0; j < 32; j++) {
            float4 kv = kr[j];
            #pragma unroll
            for (int a = 0; a < 8; a++) {
                float4 qv = ((const float4*)(qs + a * 128))[j];
                lg[a] += kv.x*qv.x + kv.y*qv.y + kv.z*qv.z + kv.w*qv.w;
            }
        }
        #pragma unroll
        for (int a = 0; a < 8; a++) {
            float v = lg[a] * SCALE_D;
            probs[a * 2048 + n] = v;
            lmax[a] = fmaxf(lmax[a], v);
        }
    }
    #pragma unroll
    for (int a = 0; a < 8; a++) {
        #pragma unroll
        for (int o = 16; o; o >>= 1) lmax[a] = fmaxf(lmax[a], __shfl_xor_sync(0xffffffffu, lmax[a], o));
    }
    if (lane == 0)
        #pragma unroll
        for (int a = 0; a < 8; a++) red[warp * 8 + a] = lmax[a];
    __syncthreads();
    if (tid < 8) {
        float m = -1e30f;
        #pragma unroll
        for (int w = 0; w < 8; w++) m = fmaxf(m, red[w * 8 + tid]);
        Mv[tid] = m;
    }
    __syncthreads();

    float lsum[8];
    #pragma unroll
    for (int a = 0; a < 8; a++) lsum[a] = 0.f;
    #pragma unroll
    for (int i = 0; i < 8; i++) {
        int n = tid + i * 256;
        #pragma unroll
        for (int a = 0; a < 8; a++) {
            float e = __expf(probs[a * 2048 + n] - Mv[a]);
            probs[a * 2048 + n] = e;
            lsum[a] += e;
        }
    }
    #pragma unroll
    for (int a = 0; a < 8; a++) {
        #pragma unroll
        for (int o = 16; o; o >>= 1) lsum[a] += __shfl_xor_sync(0xffffffffu, lsum[a], o);
    }
    __syncthreads();
    if (lane == 0)
        #pragma unroll
        for (int a = 0; a < 8; a++) red[warp * 8 + a] = lsum[a];
    __syncthreads();
    if (tid < 8) {
        float s = 0.f;
        #pragma unroll
        for (int w = 0; w < 8; w++) s += red[w * 8 + tid];
        invS[tid] = 1.0f / s;
    }
    __syncthreads();

    const int d = tid & 127, hf = tid >> 7;
    float acc[8];
    #pragma unroll
    for (int a = 0; a < 8; a++) acc[a] = 0.f;
    const int nbase = hf * 1024;
    for (int n4 = 0; n4 < 256; n4++) {
        int n = nbase + n4 * 4;
        float4 pv[8];
        #pragma unroll
        for (int a = 0; a < 8; a++) pv[a] = *(const float4*)(probs + a * 2048 + n);
        #pragma unroll
        for (int t = 0; t < 4; t++) {
            float v = g_qkv[(((size_t)(b * NQL + n + t)) * 3 + 2) * AHD + h * DDIM + d];
            #pragma unroll
            for (int a = 0; a < 8; a++) {
                float p = (t == 0) ? pv[a].x : (t == 1) ? pv[a].y : (t == 2) ? pv[a].z : pv[a].w;
                acc[a] += p * v;
            }
        }
    }
    if (hf)
        #pragma unroll
        for (int a = 0; a < 8; a++) halfbuf[a * 128 + d] = acc[a];
    __syncthreads();
    if (!hf)
        #pragma unroll
        for (int a = 0; a < 8; a++)
            g_att1[(((size_t)(b * 8 + h)) * 8 + a) * 128 + d] = (acc[a] + halfbuf[a * 128 + d]) * invS[a];
}

// ---------------- attention 2: writes y as fp16 ----------------
__global__ __launch_bounds__(128) void attn2_kernel() {
    const int nc = blockIdx.x;
    const int h  = blockIdx.y;
    const int b  = blockIdx.z;
    const int tid = threadIdx.x;
    __shared__ __align__(16) float kks[8][128];
    __shared__ __align__(16) float ovs[8][128];
    __shared__ float ps[128][9];
    #pragma unroll
    for (int r = 0; r < 8; r++) {
        kks[r][tid] = g_kkb [((size_t)(b * 8 + r)) * AHD + h * 128 + tid];
        ovs[r][tid] = g_out3[((size_t)(b * 8 + r)) * AHD + h * 128 + tid];
    }
    __syncthreads();
    const int n = nc * 128 + tid;
    const float4* qr = (const float4*)(g_qkv + ((size_t)(b * NQL + n)) * 3 * AHD + h * 128);
    float lg[8];
    #pragma unroll
    for (int aa = 0; aa < 8; aa++) lg[aa] = 0.f;
    #pragma unroll
    for (int j = 0; j < 32; j++) {
        float4 qv = qr[j];
        #pragma unroll
        for (int aa = 0; aa < 8; aa++) {
            float4 kv = ((const float4*)kks[aa])[j];
            lg[aa] += qv.x*kv.x + qv.y*kv.y + qv.z*kv.z + qv.w*kv.w;
        }
    }
    float m = -1e30f;
    #pragma unroll
    for (int aa = 0; aa < 8; aa++) { lg[aa] *= SCALE_D; m = fmaxf(m, lg[aa]); }
    float s = 0.f;
    #pragma unroll
    for (int aa = 0; aa < 8; aa++) { lg[aa] = __expf(lg[aa] - m); s += lg[aa]; }
    float inv = 1.0f / s;
    #pragma unroll
    for (int aa = 0; aa < 8; aa++) ps[tid][aa] = lg[aa] * inv;
    __syncthreads();
    for (int i = 0; i < 128; i++) {
        float acc = 0.f;
        #pragma unroll
        for (int aa = 0; aa < 8; aa++) acc += ps[i][aa] * ovs[aa][tid];
        size_t idx = ((size_t)(b * NQL) + nc * 128 + i) * AHD + h * 128 + tid;
        g_yh[idx] = __float2half_rn(acc);
    }
}

// ---------------- host orchestration ----------------
extern "C" void kernel_launch(void* const* d_in, const int* in_sizes, int n_in,
                              void* d_out, int out_size) {
    (void)in_sizes; (void)n_in; (void)out_size;
    const float* inputs   = (const float*)d_in[0];
    const float* ln_g     = (const float*)d_in[1];
    const float* ln_b     = (const float*)d_in[2];
    const float* q_anchor = (const float*)d_in[3];
    const float* W_qkv    = (const float*)d_in[4];
    const float* b_qkv    = (const float*)d_in[5];
    const float* W_an     = (const float*)d_in[6];
    const float* b_an     = (const float*)d_in[7];
    const float* W_n1     = (const float*)d_in[8];
    const float* b_n1     = (const float*)d_in[9];
    const float* W_n2     = (const float*)d_in[10];
    const float* b_n2     = (const float*)d_in[11];
    const float* W_n3     = (const float*)d_in[12];
    const float* b_n3     = (const float*)d_in[13];
    const float* W_k      = (const float*)d_in[14];
    const float* b_k      = (const float*)d_in[15];
    const float* W_o      = (const float*)d_in[16];
    const float* b_o      = (const float*)d_in[17];
    float* out = (float*)d_out;

    float *qkv, *att1, *netin, *n1, *n2, *out3, *kk, *part;
    __half *xh, *yh, *wqh, *woh;
    cudaGetSymbolAddress((void**)&qkv,  g_qkv);
    cudaGetSymbolAddress((void**)&att1, g_att1);
    cudaGetSymbolAddress((void**)&netin,g_netin);
    cudaGetSymbolAddress((void**)&n1,   g_n1);
    cudaGetSymbolAddress((void**)&n2,   g_n2);
    cudaGetSymbolAddress((void**)&out3, g_out3);
    cudaGetSymbolAddress((void**)&kk,   g_kkb);
    cudaGetSymbolAddress((void**)&part, g_part);
    cudaGetSymbolAddress((void**)&xh,   g_xh);
    cudaGetSymbolAddress((void**)&yh,   g_yh);
    cudaGetSymbolAddress((void**)&wqh,  g_wqh);
    cudaGetSymbolAddress((void**)&woh,  g_woh);

    static int attr_done = 0;
    if (!attr_done) {
        cudaFuncSetAttribute(gemm_hmma, cudaFuncAttributeMaxDynamicSharedMemorySize, 3 * GSTAGE);
        cudaFuncSetAttribute(attn1_kernel, cudaFuncAttributeMaxDynamicSharedMemorySize, 74112);
        attr_done = 1;
    }

    // weight conversion (transpose to [N,K] fp16)
    convw_kernel<<<dim3(3072/32, 1024/32), 256>>>(W_qkv, wqh, 1024, 3072);
    convw_kernel<<<dim3(1024/32, 1024/32), 256>>>(W_o,   woh, 1024, 1024);

    // LN -> fp16
    ln_kernel<<<MROWS, 256>>>(inputs, ln_g, ln_b);

    // qkv = x @ W_qkv + b_qkv     (HMMA, 16384 x 3072 x 1024)
    gemm_hmma<<<dim3(3072/128, MROWS/128), 256, 3*GSTAGE>>>(
        3072, 1024, xh, wqh, b_qkv, nullptr, qkv);

    // attention 1
    attn1_kernel<<<BB * HH, 256, 74112>>>(q_anchor);

    // middle MLP chain (fp32 split-K)
    sgemm_splitk64<<<dim3(4096/64, 1, 8), 256>>>(4096, 1024, 128, att1, W_an, part);
    reduce_bias_act<<<(64*4096 + 255)/256, 256>>>(part, b_an, netin, 4096, 1, 1);
    sgemm_splitk64<<<dim3(1024/64, 1, 8), 256>>>(1024, 4096, 512, netin, W_n1, part);
    reduce_bias_act<<<(64*1024 + 255)/256, 256>>>(part, b_n1, n1, 1024, 0, 0);
    sgemm_splitk64<<<dim3(4096/64, 1, 8), 256>>>(4096, 1024, 128, n1, W_n2, part);
    reduce_bias_act<<<(64*4096 + 255)/256, 256>>>(part, b_n2, n2, 4096, 1, 0);
    sgemm_splitk64<<<dim3(1024/64, 1, 8), 256>>>(1024, 4096, 512, n2, W_n3, part);
    reduce_bias_act<<<(64*1024 + 255)/256, 256>>>(part, b_n3, out3, 1024, 0, 0);
    sgemm_splitk64<<<dim3(1024/64, 1, 8), 256>>>(1024, 1024, 128, out3, W_k, part);
    reduce_bias_act<<<(64*1024 + 255)/256, 256>>>(part, b_k, kk, 1024, 0, 0);

    // attention 2 (-> fp16 y)
    attn2_kernel<<<dim3(NQL/128, HH, BB), 128>>>();

    // out = y @ W_o + b_o + inputs   (HMMA, 16384 x 1024 x 1024)
    gemm_hmma<<<dim3(1024/128, MROWS/128), 256, 3*GSTAGE>>>(
        1024, 1024, yh, woh, b_o, inputs, out);
}

// round 5
// speedup vs baseline: 3.7410x; 1.0908x over previous
#include <cuda_runtime.h>
#include <cuda_fp16.h>
#include <cstdint>

// ---------------- problem constants ----------------
#define BB     8
#define NQL    2048
#define ISZ    1024
#define HH     8
#define DDIM   128
#define NAA    8
#define AHD    1024
#define FHD    4096
#define MROWS  (BB*NQL)  // 16384
#define SCALE_D 0.08838834764831845f

// ---------------- static scratch ----------------
__device__ __half g_xh [(size_t)MROWS * ISZ];
__device__ float  g_qkv[(size_t)MROWS * 3 * AHD];
__device__ __half g_yh [(size_t)MROWS * AHD];
__device__ __half g_wqh[3072 * 1024];   // W_qkv^T  [N,K]
__device__ __half g_woh[1024 * 1024];   // W_o^T
__device__ __half g_want[4096 * 1024];  // W_an^T
__device__ __half g_wn1t[1024 * 4096];  // W_n1^T
__device__ __half g_wn2t[4096 * 1024];  // W_n2^T
__device__ __half g_wn3t[1024 * 4096];  // W_n3^T
__device__ __half g_wkt [1024 * 1024];  // W_k^T
__device__ __half g_att1h [64 * 1024];
__device__ __half g_netinh[64 * 4096];
__device__ __half g_n1h   [64 * 1024];
__device__ __half g_n2h   [64 * 4096];
__device__ __half g_out3h [64 * 1024];
__device__ float  g_out3  [64 * 1024];
__device__ float  g_kkb   [64 * 1024];
__device__ float  g_part  [16 * 64 * 4096];

// ---------------- helpers ----------------
__device__ __forceinline__ uint32_t smem_u32(const void* p) {
    uint32_t a;
    asm("{ .reg .u64 t; cvta.to.shared.u64 t, %1; cvt.u32.u64 %0, t; }" : "=r"(a) : "l"(p));
    return a;
}
__device__ __forceinline__ void cp16(uint32_t dst, const void* src) {
    asm volatile("cp.async.cg.shared.global [%0], [%1], 16;" :: "r"(dst), "l"(src) : "memory");
}
__device__ __forceinline__ void cp_commit() {
    asm volatile("cp.async.commit_group;" ::: "memory");
}
__device__ __forceinline__ void cp_wait2() {
    asm volatile("cp.async.wait_group 2;" ::: "memory");
}

#define LDM4(r, addr) \
    asm volatile("ldmatrix.sync.aligned.m8n8.x4.shared.b16 {%0,%1,%2,%3}, [%4];" \
                 : "=r"((r)[0]), "=r"((r)[1]), "=r"((r)[2]), "=r"((r)[3]) : "r"(addr))

#define MMA16816(d, a, b0, b1) \
    asm volatile("mma.sync.aligned.m16n8k16.row.col.f32.f16.f16.f32 " \
                 "{%0,%1,%2,%3}, {%4,%5,%6,%7}, {%8,%9}, {%0,%1,%2,%3};" \
                 : "+f"((d)[0]), "+f"((d)[1]), "+f"((d)[2]), "+f"((d)[3]) \
                 : "r"((a)[0]), "r"((a)[1]), "r"((a)[2]), "r"((a)[3]), "r"(b0), "r"(b1))

// ---------------- LayerNorm -> fp16 ----------------
__global__ __launch_bounds__(256) void ln_kernel(const float* __restrict__ in,
                                                 const float* __restrict__ gam,
                                                 const float* __restrict__ bet) {
    int row = blockIdx.x;
    int tid = threadIdx.x;
    const float4 v = ((const float4*)(in + (size_t)row * ISZ))[tid];
    float s  = v.x + v.y + v.z + v.w;
    float ss = v.x*v.x + v.y*v.y + v.z*v.z + v.w*v.w;
    __shared__ float r1[32], r2[32];
    #pragma unroll
    for (int o = 16; o; o >>= 1) {
        s  += __shfl_xor_sync(0xffffffffu, s,  o);
        ss += __shfl_xor_sync(0xffffffffu, ss, o);
    }
    if ((tid & 31) == 0) { r1[tid >> 5] = s; r2[tid >> 5] = ss; }
    __syncthreads();
    if (tid < 32) {
        float a = (tid < 8) ? r1[tid] : 0.f;
        float b = (tid < 8) ? r2[tid] : 0.f;
        #pragma unroll
        for (int o = 4; o; o >>= 1) {
            a += __shfl_xor_sync(0xffffffffu, a, o);
            b += __shfl_xor_sync(0xffffffffu, b, o);
        }
        if (tid == 0) { r1[0] = a; r2[0] = b; }
    }
    __syncthreads();
    float mean = r1[0] * (1.0f / ISZ);
    float var  = r2[0] * (1.0f / ISZ) - mean * mean;
    float rstd = rsqrtf(var + 1e-6f);
    const float4 g4 = ((const float4*)gam)[tid];
    const float4 b4 = ((const float4*)bet)[tid];
    float o0 = (v.x - mean) * rstd * g4.x + b4.x;
    float o1 = (v.y - mean) * rstd * g4.y + b4.y;
    float o2 = (v.z - mean) * rstd * g4.z + b4.z;
    float o3 = (v.w - mean) * rstd * g4.w + b4.w;
    __half2* ph = (__half2*)(g_xh + (size_t)row * ISZ);
    ph[tid*2]   = __halves2half2(__float2half_rn(o0), __float2half_rn(o1));
    ph[tid*2+1] = __halves2half2(__float2half_rn(o2), __float2half_rn(o3));
}

// ---------------- weight transpose: W[K][N] -> Wh [N][K] fp16 ----------------
__global__ __launch_bounds__(256) void convw_kernel(const float* __restrict__ W,
                                                    __half* __restrict__ Wh,
                                                    int K, int N) {
    __shared__ float t[32][33];
    int n0 = blockIdx.x * 32, k0 = blockIdx.y * 32;
    int tx = threadIdx.x & 31, ty = threadIdx.x >> 5;
    #pragma unroll
    for (int i = 0; i < 4; i++)
        t[ty + i*8][tx] = W[(size_t)(k0 + ty + i*8) * N + n0 + tx];
    __syncthreads();
    #pragma unroll
    for (int i = 0; i < 4; i++) {
        int nn = ty + i*8;
        Wh[(size_t)(n0 + nn) * K + k0 + tx] = __float2half_rn(t[tx][nn]);
    }
}

// ---------------- HMMA fp16 GEMM (big) ----------------
// CTA 128x128, 8 warps 2(M)x4(N), K-chunk 32, 4-stage cp.async, 1 barrier/chunk.
#define GSTAGE 20480
#define MAT_B  10240
__global__ __launch_bounds__(256, 2)
void gemm_hmma(int N, int K,
               const __half* __restrict__ A,
               const __half* __restrict__ B,
               const float* __restrict__ bias, const float* __restrict__ resid,
               float* __restrict__ C) {
    extern __shared__ __align__(16) char dsm[];
    const int tid  = threadIdx.x;
    const int wid  = tid >> 5;
    const int lane = tid & 31;
    const int wm   = wid >> 2;
    const int wn   = wid & 3;
    const int m0   = blockIdx.y * 128;
    const int n0   = blockIdx.x * 128;
    const uint32_t dynb = smem_u32(dsm);

    float acc[4][4][4];
    #pragma unroll
    for (int i = 0; i < 4; i++)
        #pragma unroll
        for (int j = 0; j < 4; j++)
            #pragma unroll
            for (int q = 0; q < 4; q++) acc[i][j][q] = 0.f;

    const __half* srcA = A + (size_t)m0 * K;
    const __half* srcB = B + (size_t)n0 * K;
    const int NCH = K >> 5;

    auto load_chunk = [&](int chunk, int s) {
        uint32_t base = dynb + s * GSTAGE;
        int k0 = chunk * 32;
        int row = tid >> 2;
        int c4  = tid & 3;
        uint32_t off = row * 80 + c4 * 16;
        cp16(base + off,                 srcA + (size_t)row * K + k0 + c4 * 8);
        cp16(base + 5120 + off,          srcA + (size_t)(row + 64) * K + k0 + c4 * 8);
        cp16(base + MAT_B + off,         srcB + (size_t)row * K + k0 + c4 * 8);
        cp16(base + MAT_B + 5120 + off,  srcB + (size_t)(row + 64) * K + k0 + c4 * 8);
    };

    load_chunk(0, 0); cp_commit();
    load_chunk(1, 1); cp_commit();
    load_chunk(2, 2); cp_commit();

    const int arow = wm * 64 + (lane & 15);
    const int acol = (lane >> 4) * 8;
    const int brow = wn * 32 + (lane & 7) + ((lane >> 4) << 3);
    const int bcol = ((lane >> 3) & 1) * 8;

    for (int c = 0; c < NCH; c++) {
        cp_wait2();
        __syncthreads();
        if (c + 3 < NCH) load_chunk(c + 3, (c + 3) & 3);
        cp_commit();

        uint32_t base = dynb + (c & 3) * GSTAGE;
        #pragma unroll
        for (int step = 0; step < 2; step++) {
            int kb = step * 16;
            uint32_t ah4[4][4], bh4[2][4];
            #pragma unroll
            for (int mt = 0; mt < 4; mt++) {
                uint32_t off = (uint32_t)((arow + mt * 16) * 80 + (kb + acol) * 2);
                LDM4(ah4[mt], base + off);
            }
            #pragma unroll
            for (int ng = 0; ng < 2; ng++) {
                uint32_t off = (uint32_t)((brow + ng * 16) * 80 + (kb + bcol) * 2);
                LDM4(bh4[ng], base + MAT_B + off);
            }
            #pragma unroll
            for (int mt = 0; mt < 4; mt++) {
                #pragma unroll
                for (int nt = 0; nt < 4; nt++) {
                    int ng = nt >> 1, hb = (nt & 1) * 2;
                    MMA16816(acc[mt][nt], ah4[mt], bh4[ng][hb], bh4[ng][hb + 1]);
                }
            }
        }
    }

    #pragma unroll
    for (int mt = 0; mt < 4; mt++) {
        #pragma unroll
        for (int nt = 0; nt < 4; nt++) {
            int row = m0 + wm * 64 + mt * 16 + (lane >> 2);
            int col = n0 + wn * 32 + nt * 8 + (lane & 3) * 2;
            float b0 = bias[col], b1 = bias[col + 1];
            #pragma unroll
            for (int hh = 0; hh < 2; hh++) {
                int r = row + hh * 8;
                float o0 = acc[mt][nt][hh * 2 + 0] + b0;
                float o1 = acc[mt][nt][hh * 2 + 1] + b1;
                if (resid) {
                    const float2 rv = *(const float2*)(resid + (size_t)r * N + col);
                    o0 += rv.x; o1 += rv.y;
                }
                *(float2*)(C + (size_t)r * N + col) = make_float2(o0, o1);
            }
        }
    }
}

// ---------------- HMMA split-K GEMM for M=64 middle chain ----------------
// tile M=64 x N=64, 4 warps 2(M)x2(N), K-chunk 32, 4 stages. grid (N/64, S).
#define SKSTAGE 10240   // (64+64) rows x 80B
__global__ __launch_bounds__(128, 4)
void hmma_splitk(int N, int K, int kc,
                 const __half* __restrict__ A,
                 const __half* __restrict__ B,
                 float* __restrict__ part) {
    extern __shared__ __align__(16) char dsm[];
    const int tid  = threadIdx.x;
    const int wid  = tid >> 5;
    const int lane = tid & 31;
    const int wm   = wid >> 1;
    const int wn   = wid & 1;
    const int n0   = blockIdx.x * 64;
    const int z    = blockIdx.y;
    const int kb   = z * kc;
    const uint32_t dynb = smem_u32(dsm);

    float acc[2][4][4];
    #pragma unroll
    for (int i = 0; i < 2; i++)
        #pragma unroll
        for (int j = 0; j < 4; j++)
            #pragma unroll
            for (int q = 0; q < 4; q++) acc[i][j][q] = 0.f;

    const __half* srcB = B + (size_t)n0 * K;
    const int NCH = kc >> 5;

    auto load_chunk = [&](int chunk, int s) {
        uint32_t base = dynb + s * SKSTAGE;
        int k0 = kb + chunk * 32;
        int row = tid >> 1;
        int cp  = (tid & 1) * 2;
        uint32_t off = row * 80 + cp * 16;
        cp16(base + off,        A + (size_t)row * K + k0 + cp * 8);
        cp16(base + off + 16,   A + (size_t)row * K + k0 + cp * 8 + 8);
        cp16(base + 5120 + off,      srcB + (size_t)row * K + k0 + cp * 8);
        cp16(base + 5120 + off + 16, srcB + (size_t)row * K + k0 + cp * 8 + 8);
    };

    load_chunk(0, 0); cp_commit();
    if (NCH > 1) load_chunk(1, 1);
    cp_commit();
    if (NCH > 2) load_chunk(2, 2);
    cp_commit();

    const int arow = wm * 32 + (lane & 15);
    const int acol = (lane >> 4) * 8;
    const int brow = wn * 32 + (lane & 7) + ((lane >> 4) << 3);
    const int bcol = ((lane >> 3) & 1) * 8;

    for (int c = 0; c < NCH; c++) {
        cp_wait2();
        __syncthreads();
        if (c + 3 < NCH) load_chunk(c + 3, (c + 3) & 3);
        cp_commit();

        uint32_t base = dynb + (c & 3) * SKSTAGE;
        #pragma unroll
        for (int step = 0; step < 2; step++) {
            int kbb = step * 16;
            uint32_t ah4[2][4], bh4[2][4];
            #pragma unroll
            for (int mt = 0; mt < 2; mt++) {
                uint32_t off = (uint32_t)((arow + mt * 16) * 80 + (kbb + acol) * 2);
                LDM4(ah4[mt], base + off);
            }
            #pragma unroll
            for (int ng = 0; ng < 2; ng++) {
                uint32_t off = (uint32_t)((brow + ng * 16) * 80 + (kbb + bcol) * 2);
                LDM4(bh4[ng], base + 5120 + off);
            }
            #pragma unroll
            for (int mt = 0; mt < 2; mt++) {
                #pragma unroll
                for (int nt = 0; nt < 4; nt++) {
                    int ng = nt >> 1, hb = (nt & 1) * 2;
                    MMA16816(acc[mt][nt], ah4[mt], bh4[ng][hb], bh4[ng][hb + 1]);
                }
            }
        }
    }

    #pragma unroll
    for (int mt = 0; mt < 2; mt++) {
        #pragma unroll
        for (int nt = 0; nt < 4; nt++) {
            int row = wm * 32 + mt * 16 + (lane >> 2);
            int col = n0 + wn * 32 + nt * 8 + (lane & 3) * 2;
            #pragma unroll
            for (int hh = 0; hh < 2; hh++) {
                int r = row + hh * 8;
                *(float2*)(part + ((size_t)z * 64 + r) * N + col)
                    = make_float2(acc[mt][nt][hh * 2 + 0], acc[mt][nt][hh * 2 + 1]);
            }
        }
    }
}

// sum S split-K partials + bias (+relu) (+permute), emit fp32 and/or fp16
__global__ __launch_bounds__(256)
void reduce_bias_act(const float* __restrict__ part, const float* __restrict__ bias,
                     float* __restrict__ outf, __half* __restrict__ outh,
                     int N, int S, int act, int permute) {
    int idx = blockIdx.x * 256 + threadIdx.x;
    int total = 64 * N;
    if (idx >= total) return;
    int m = idx / N, n = idx - m * N;
    float s = 0.f;
    for (int zz = 0; zz < S; zz++) s += part[(size_t)zz * total + idx];
    s += bias[n];
    if (act) s = fmaxf(s, 0.f);
    int oidx = idx;
    if (permute) {
        int b = m >> 3, h = m & 7;
        int na = n >> 9, j = n & 511;
        oidx = ((b * 8 + na)) * 4096 + h * 512 + j;
    }
    if (outf) outf[oidx] = s;
    if (outh) outh[oidx] = __float2half_rn(s);
}

// ---------------- attention 1: one block per (b,h), all 8 anchors ----------------
__global__ __launch_bounds__(256) void attn1_kernel(const float* __restrict__ q_anchor) {
    extern __shared__ float a1s[];
    float* probs   = a1s;                   // [8][2048]
    float* qs      = a1s + 8 * 2048;        // [8][128]
    float* halfbuf = qs + 8 * 128;          // [8][128]
    float* red     = halfbuf + 8 * 128;     // [8 warps][8]
    float* Mv      = red + 64;              // [8]
    float* invS    = Mv + 8;                // [8]
    const int h = blockIdx.x & 7;
    const int b = blockIdx.x >> 3;
    const int tid = threadIdx.x;
    const int warp = tid >> 5, lane = tid & 31;

    for (int i = tid; i < 1024; i += 256) qs[i] = q_anchor[h * 1024 + i];
    __syncthreads();

    float lmax[8];
    #pragma unroll
    for (int a = 0; a < 8; a++) lmax[a] = -1e30f;
    #pragma unroll
    for (int i = 0; i < 8; i++) {
        int n = tid + i * 256;
        const float4* kr = (const float4*)(g_qkv + (((size_t)(b * NQL + n)) * 3 + 1) * AHD + h * DDIM);
        float lg[8];
        #pragma unroll
        for (int a = 0; a < 8; a++) lg[a] = 0.f;
        #pragma unroll
        for (int j = 0; j < 32; j++) {
            float4 kv = kr[j];
            #pragma unroll
            for (int a = 0; a < 8; a++) {
                float4 qv = ((const float4*)(qs + a * 128))[j];
                lg[a] += kv.x*qv.x + kv.y*qv.y + kv.z*qv.z + kv.w*qv.w;
            }
        }
        #pragma unroll
        for (int a = 0; a < 8; a++) {
            float v = lg[a] * SCALE_D;
            probs[a * 2048 + n] = v;
            lmax[a] = fmaxf(lmax[a], v);
        }
    }
    #pragma unroll
    for (int a = 0; a < 8; a++) {
        #pragma unroll
        for (int o = 16; o; o >>= 1) lmax[a] = fmaxf(lmax[a], __shfl_xor_sync(0xffffffffu, lmax[a], o));
    }
    if (lane == 0)
        #pragma unroll
        for (int a = 0; a < 8; a++) red[warp * 8 + a] = lmax[a];
    __syncthreads();
    if (tid < 8) {
        float m = -1e30f;
        #pragma unroll
        for (int w = 0; w < 8; w++) m = fmaxf(m, red[w * 8 + tid]);
        Mv[tid] = m;
    }
    __syncthreads();

    float lsum[8];
    #pragma unroll
    for (int a = 0; a < 8; a++) lsum[a] = 0.f;
    #pragma unroll
    for (int i = 0; i < 8; i++) {
        int n = tid + i * 256;
        #pragma unroll
        for (int a = 0; a < 8; a++) {
            float e = __expf(probs[a * 2048 + n] - Mv[a]);
            probs[a * 2048 + n] = e;
            lsum[a] += e;
        }
    }
    #pragma unroll
    for (int a = 0; a < 8; a++) {
        #pragma unroll
        for (int o = 16; o; o >>= 1) lsum[a] += __shfl_xor_sync(0xffffffffu, lsum[a], o);
    }
    __syncthreads();
    if (lane == 0)
        #pragma unroll
        for (int a = 0; a < 8; a++) red[warp * 8 + a] = lsum[a];
    __syncthreads();
    if (tid < 8) {
        float s = 0.f;
        #pragma unroll
        for (int w = 0; w < 8; w++) s += red[w * 8 + tid];
        invS[tid] = 1.0f / s;
    }
    __syncthreads();

    const int d = tid & 127, hf = tid >> 7;
    float acc[8];
    #pragma unroll
    for (int a = 0; a < 8; a++) acc[a] = 0.f;
    const int nbase = hf * 1024;
    for (int n4 = 0; n4 < 256; n4++) {
        int n = nbase + n4 * 4;
        float4 pv[8];
        #pragma unroll
        for (int a = 0; a < 8; a++) pv[a] = *(const float4*)(probs + a * 2048 + n);
        #pragma unroll
        for (int t = 0; t < 4; t++) {
            float v = g_qkv[(((size_t)(b * NQL + n + t)) * 3 + 2) * AHD + h * DDIM + d];
            #pragma unroll
            for (int a = 0; a < 8; a++) {
                float p = (t == 0) ? pv[a].x : (t == 1) ? pv[a].y : (t == 2) ? pv[a].z : pv[a].w;
                acc[a] += p * v;
            }
        }
    }
    if (hf)
        #pragma unroll
        for (int a = 0; a < 8; a++) halfbuf[a * 128 + d] = acc[a];
    __syncthreads();
    if (!hf)
        #pragma unroll
        for (int a = 0; a < 8; a++)
            g_att1h[(((size_t)(b * 8 + h)) * 8 + a) * 128 + d]
                = __float2half_rn((acc[a] + halfbuf[a * 128 + d]) * invS[a]);
}

// ---------------- attention 2: writes y as fp16 ----------------
__global__ __launch_bounds__(128) void attn2_kernel() {
    const int nc = blockIdx.x;
    const int h  = blockIdx.y;
    const int b  = blockIdx.z;
    const int tid = threadIdx.x;
    __shared__ __align__(16) float kks[8][128];
    __shared__ __align__(16) float ovs[8][128];
    __shared__ float ps[128][9];
    #pragma unroll
    for (int r = 0; r < 8; r++) {
        kks[r][tid] = g_kkb [((size_t)(b * 8 + r)) * AHD + h * 128 + tid];
        ovs[r][tid] = g_out3[((size_t)(b * 8 + r)) * AHD + h * 128 + tid];
    }
    __syncthreads();
    const int n = nc * 128 + tid;
    const float4* qr = (const float4*)(g_qkv + ((size_t)(b * NQL + n)) * 3 * AHD + h * 128);
    float lg[8];
    #pragma unroll
    for (int aa = 0; aa < 8; aa++) lg[aa] = 0.f;
    #pragma unroll
    for (int j = 0; j < 32; j++) {
        float4 qv = qr[j];
        #pragma unroll
        for (int aa = 0; aa < 8; aa++) {
            float4 kv = ((const float4*)kks[aa])[j];
            lg[aa] += qv.x*kv.x + qv.y*kv.y + qv.z*kv.z + qv.w*kv.w;
        }
    }
    float m = -1e30f;
    #pragma unroll
    for (int aa = 0; aa < 8; aa++) { lg[aa] *= SCALE_D; m = fmaxf(m, lg[aa]); }
    float s = 0.f;
    #pragma unroll
    for (int aa = 0; aa < 8; aa++) { lg[aa] = __expf(lg[aa] - m); s += lg[aa]; }
    float inv = 1.0f / s;
    #pragma unroll
    for (int aa = 0; aa < 8; aa++) ps[tid][aa] = lg[aa] * inv;
    __syncthreads();
    for (int i = 0; i < 128; i++) {
        float acc = 0.f;
        #pragma unroll
        for (int aa = 0; aa < 8; aa++) acc += ps[i][aa] * ovs[aa][tid];
        size_t idx = ((size_t)(b * NQL) + nc * 128 + i) * AHD + h * 128 + tid;
        g_yh[idx] = __float2half_rn(acc);
    }
}

// ---------------- host orchestration ----------------
extern "C" void kernel_launch(void* const* d_in, const int* in_sizes, int n_in,
                              void* d_out, int out_size) {
    (void)in_sizes; (void)n_in; (void)out_size;
    const float* inputs   = (const float*)d_in[0];
    const float* ln_g     = (const float*)d_in[1];
    const float* ln_b     = (const float*)d_in[2];
    const float* q_anchor = (const float*)d_in[3];
    const float* W_qkv    = (const float*)d_in[4];
    const float* b_qkv    = (const float*)d_in[5];
    const float* W_an     = (const float*)d_in[6];
    const float* b_an     = (const float*)d_in[7];
    const float* W_n1     = (const float*)d_in[8];
    const float* b_n1     = (const float*)d_in[9];
    const float* W_n2     = (const float*)d_in[10];
    const float* b_n2     = (const float*)d_in[11];
    const float* W_n3     = (const float*)d_in[12];
    const float* b_n3     = (const float*)d_in[13];
    const float* W_k      = (const float*)d_in[14];
    const float* b_k      = (const float*)d_in[15];
    const float* W_o      = (const float*)d_in[16];
    const float* b_o      = (const float*)d_in[17];
    float* out = (float*)d_out;

    float *qkv, *out3, *kk, *part;
    __half *xh, *yh, *wqh, *woh, *want, *wn1t, *wn2t, *wn3t, *wkt;
    __half *att1h, *netinh, *n1h, *n2h, *out3h;
    cudaGetSymbolAddress((void**)&qkv,   g_qkv);
    cudaGetSymbolAddress((void**)&out3,  g_out3);
    cudaGetSymbolAddress((void**)&kk,    g_kkb);
    cudaGetSymbolAddress((void**)&part,  g_part);
    cudaGetSymbolAddress((void**)&xh,    g_xh);
    cudaGetSymbolAddress((void**)&yh,    g_yh);
    cudaGetSymbolAddress((void**)&wqh,   g_wqh);
    cudaGetSymbolAddress((void**)&woh,   g_woh);
    cudaGetSymbolAddress((void**)&want,  g_want);
    cudaGetSymbolAddress((void**)&wn1t,  g_wn1t);
    cudaGetSymbolAddress((void**)&wn2t,  g_wn2t);
    cudaGetSymbolAddress((void**)&wn3t,  g_wn3t);
    cudaGetSymbolAddress((void**)&wkt,   g_wkt);
    cudaGetSymbolAddress((void**)&att1h, g_att1h);
    cudaGetSymbolAddress((void**)&netinh,g_netinh);
    cudaGetSymbolAddress((void**)&n1h,   g_n1h);
    cudaGetSymbolAddress((void**)&n2h,   g_n2h);
    cudaGetSymbolAddress((void**)&out3h, g_out3h);

    static int attr_done = 0;
    if (!attr_done) {
        cudaFuncSetAttribute(gemm_hmma, cudaFuncAttributeMaxDynamicSharedMemorySize, 4 * GSTAGE);
        cudaFuncSetAttribute(hmma_splitk, cudaFuncAttributeMaxDynamicSharedMemorySize, 4 * SKSTAGE);
        cudaFuncSetAttribute(attn1_kernel, cudaFuncAttributeMaxDynamicSharedMemorySize, 74112);
        attr_done = 1;
    }

    // weight conversion (transpose to [N,K] fp16)
    convw_kernel<<<dim3(3072/32, 1024/32), 256>>>(W_qkv, wqh, 1024, 3072);
    convw_kernel<<<dim3(1024/32, 1024/32), 256>>>(W_o,   woh, 1024, 1024);
    convw_kernel<<<dim3(4096/32, 1024/32), 256>>>(W_an,  want, 1024, 4096);
    convw_kernel<<<dim3(1024/32, 4096/32), 256>>>(W_n1,  wn1t, 4096, 1024);
    convw_kernel<<<dim3(4096/32, 1024/32), 256>>>(W_n2,  wn2t, 1024, 4096);
    convw_kernel<<<dim3(1024/32, 4096/32), 256>>>(W_n3,  wn3t, 4096, 1024);
    convw_kernel<<<dim3(1024/32, 1024/32), 256>>>(W_k,   wkt,  1024, 1024);

    // LN -> fp16
    ln_kernel<<<MROWS, 256>>>(inputs, ln_g, ln_b);

    // qkv = x @ W_qkv + b_qkv     (HMMA, 16384 x 3072 x 1024)
    gemm_hmma<<<dim3(3072/128, MROWS/128), 256, 4*GSTAGE>>>(
        3072, 1024, xh, wqh, b_qkv, nullptr, qkv);

    // attention 1 -> fp16 att1h
    attn1_kernel<<<BB * HH, 256, 74112>>>(q_anchor);

    // middle MLP chain (fp16 HMMA split-K)
    hmma_splitk<<<dim3(4096/64, 8), 128, 4*SKSTAGE>>>(4096, 1024, 128, att1h, want, part);
    reduce_bias_act<<<(64*4096+255)/256, 256>>>(part, b_an, nullptr, netinh, 4096, 8, 1, 1);
    hmma_splitk<<<dim3(1024/64, 16), 128, 4*SKSTAGE>>>(1024, 4096, 256, netinh, wn1t, part);
    reduce_bias_act<<<(64*1024+255)/256, 256>>>(part, b_n1, nullptr, n1h, 1024, 16, 0, 0);
    hmma_splitk<<<dim3(4096/64, 8), 128, 4*SKSTAGE>>>(4096, 1024, 128, n1h, wn2t, part);
    reduce_bias_act<<<(64*4096+255)/256, 256>>>(part, b_n2, nullptr, n2h, 4096, 8, 1, 0);
    hmma_splitk<<<dim3(1024/64, 16), 128, 4*SKSTAGE>>>(1024, 4096, 256, n2h, wn3t, part);
    reduce_bias_act<<<(64*1024+255)/256, 256>>>(part, b_n3, out3, out3h, 1024, 16, 0, 0);
    hmma_splitk<<<dim3(1024/64, 8), 128, 4*SKSTAGE>>>(1024, 1024, 128, out3h, wkt, part);
    reduce_bias_act<<<(64*1024+255)/256, 256>>>(part, b_k, kk, nullptr, 1024, 8, 0, 0);

    // attention 2 (-> fp16 y)
    attn2_kernel<<<dim3(NQL/128, HH, BB), 128>>>();

    // out = y @ W_o + b_o + inputs   (HMMA, 16384 x 1024 x 1024)
    gemm_hmma<<<dim3(1024/128, MROWS/128), 256, 4*GSTAGE>>>(
        1024, 1024, yh, woh, b_o, inputs, out);
}

// round 9
// speedup vs baseline: 3.8974x; 1.0418x over previous
#include <cuda_runtime.h>
#include <cuda_fp16.h>
#include <cstdint>

// ---------------- problem constants ----------------
#define BB     8
#define NQL    2048
#define ISZ    1024
#define HH     8
#define DDIM   128
#define NAA    8
#define AHD    1024
#define FHD    4096
#define MROWS  (BB*NQL)  // 16384
#define SCALE_D 0.08838834764831845f

// ---------------- static scratch ----------------
__device__ __half g_xh [(size_t)MROWS * ISZ];
__device__ float  g_qkv[(size_t)MROWS * 3 * AHD];
__device__ __half g_yh [(size_t)MROWS * AHD];
__device__ __half g_wqh[3072 * 1024];   // W_qkv^T  [N,K]
__device__ __half g_woh[1024 * 1024];   // W_o^T
__device__ __half g_want[4096 * 1024];  // W_an^T
__device__ __half g_wn1t[1024 * 4096];  // W_n1^T
__device__ __half g_wn2t[4096 * 1024];  // W_n2^T
__device__ __half g_wn3t[1024 * 4096];  // W_n3^T
__device__ __half g_wkt [1024 * 1024];  // W_k^T
__device__ __half g_att1h [64 * 1024];
__device__ __half g_netinh[64 * 4096];
__device__ __half g_n1h   [64 * 1024];
__device__ __half g_n2h   [64 * 4096];
__device__ __half g_out3h [64 * 1024];
__device__ float  g_out3  [64 * 1024];
__device__ float  g_kkb   [64 * 1024];
__device__ float  g_part  [16 * 64 * 4096];

// ---------------- helpers ----------------
__device__ __forceinline__ uint32_t smem_u32(const void* p) {
    uint32_t a;
    asm("{ .reg .u64 t; cvta.to.shared.u64 t, %1; cvt.u32.u64 %0, t; }" : "=r"(a) : "l"(p));
    return a;
}
__device__ __forceinline__ void cp16(uint32_t dst, const void* src) {
    asm volatile("cp.async.cg.shared.global [%0], [%1], 16;" :: "r"(dst), "l"(src) : "memory");
}
__device__ __forceinline__ void cp_commit() {
    asm volatile("cp.async.commit_group;" ::: "memory");
}
__device__ __forceinline__ void cp_wait1() {
    asm volatile("cp.async.wait_group 1;" ::: "memory");
}
__device__ __forceinline__ void cp_wait2() {
    asm volatile("cp.async.wait_group 2;" ::: "memory");
}

#define LDM4(r, addr) \
    asm volatile("ldmatrix.sync.aligned.m8n8.x4.shared.b16 {%0,%1,%2,%3}, [%4];" \
                 : "=r"((r)[0]), "=r"((r)[1]), "=r"((r)[2]), "=r"((r)[3]) : "r"(addr))

#define MMA16816(d, a, b0, b1) \
    asm volatile("mma.sync.aligned.m16n8k16.row.col.f32.f16.f16.f32 " \
                 "{%0,%1,%2,%3}, {%4,%5,%6,%7}, {%8,%9}, {%0,%1,%2,%3};" \
                 : "+f"((d)[0]), "+f"((d)[1]), "+f"((d)[2]), "+f"((d)[3]) \
                 : "r"((a)[0]), "r"((a)[1]), "r"((a)[2]), "r"((a)[3]), "r"(b0), "r"(b1))

// ---------------- LayerNorm -> fp16 ----------------
__global__ __launch_bounds__(256) void ln_kernel(const float* __restrict__ in,
                                                 const float* __restrict__ gam,
                                                 const float* __restrict__ bet) {
    int row = blockIdx.x;
    int tid = threadIdx.x;
    const float4 v = ((const float4*)(in + (size_t)row * ISZ))[tid];
    float s  = v.x + v.y + v.z + v.w;
    float ss = v.x*v.x + v.y*v.y + v.z*v.z + v.w*v.w;
    __shared__ float r1[32], r2[32];
    #pragma unroll
    for (int o = 16; o; o >>= 1) {
        s  += __shfl_xor_sync(0xffffffffu, s,  o);
        ss += __shfl_xor_sync(0xffffffffu, ss, o);
    }
    if ((tid & 31) == 0) { r1[tid >> 5] = s; r2[tid >> 5] = ss; }
    __syncthreads();
    if (tid < 32) {
        float a = (tid < 8) ? r1[tid] : 0.f;
        float b = (tid < 8) ? r2[tid] : 0.f;
        #pragma unroll
        for (int o = 4; o; o >>= 1) {
            a += __shfl_xor_sync(0xffffffffu, a, o);
            b += __shfl_xor_sync(0xffffffffu, b, o);
        }
        if (tid == 0) { r1[0] = a; r2[0] = b; }
    }
    __syncthreads();
    float mean = r1[0] * (1.0f / ISZ);
    float var  = r2[0] * (1.0f / ISZ) - mean * mean;
    float rstd = rsqrtf(var + 1e-6f);
    const float4 g4 = ((const float4*)gam)[tid];
    const float4 b4 = ((const float4*)bet)[tid];
    float o0 = (v.x - mean) * rstd * g4.x + b4.x;
    float o1 = (v.y - mean) * rstd * g4.y + b4.y;
    float o2 = (v.z - mean) * rstd * g4.z + b4.z;
    float o3 = (v.w - mean) * rstd * g4.w + b4.w;
    __half2* ph = (__half2*)(g_xh + (size_t)row * ISZ);
    ph[tid*2]   = __halves2half2(__float2half_rn(o0), __float2half_rn(o1));
    ph[tid*2+1] = __halves2half2(__float2half_rn(o2), __float2half_rn(o3));
}

// ---------------- weight transpose: W[K][N] -> Wh [N][K] fp16 ----------------
__global__ __launch_bounds__(256) void convw_kernel(const float* __restrict__ W,
                                                    __half* __restrict__ Wh,
                                                    int K, int N) {
    __shared__ float t[32][33];
    int n0 = blockIdx.x * 32, k0 = blockIdx.y * 32;
    int tx = threadIdx.x & 31, ty = threadIdx.x >> 5;
    #pragma unroll
    for (int i = 0; i < 4; i++)
        t[ty + i*8][tx] = W[(size_t)(k0 + ty + i*8) * N + n0 + tx];
    __syncthreads();
    #pragma unroll
    for (int i = 0; i < 4; i++) {
        int nn = ty + i*8;
        Wh[(size_t)(n0 + nn) * K + k0 + tx] = __float2half_rn(t[tx][nn]);
    }
}

// ---------------- HMMA fp16 GEMM: 128x128 tile, K-chunk 64, 3-stage cp.async ----------------
// smem stage: A 128 rows + B 128 rows, pitch 144B (64 halfs + 8 pad) -> 36864 B.
#define GP      144
#define GSTAGE  36864
#define GB_OFF  18432
__global__ __launch_bounds__(256, 2)
void gemm_hmma(int N, int K,
               const __half* __restrict__ A,
               const __half* __restrict__ B,
               const float* __restrict__ bias, const float* __restrict__ resid,
               float* __restrict__ C) {
    extern __shared__ __align__(16) char dsm[];
    const int tid  = threadIdx.x;
    const int wid  = tid >> 5;
    const int lane = tid & 31;
    const int wm   = wid >> 2;
    const int wn   = wid & 3;
    const int m0   = blockIdx.y * 128;
    const int n0   = blockIdx.x * 128;
    const uint32_t dynb = smem_u32(dsm);

    float acc[4][4][4];
    #pragma unroll
    for (int i = 0; i < 4; i++)
        #pragma unroll
        for (int j = 0; j < 4; j++)
            #pragma unroll
            for (int q = 0; q < 4; q++) acc[i][j][q] = 0.f;

    const __half* srcA = A + (size_t)m0 * K;
    const __half* srcB = B + (size_t)n0 * K;
    const int NCH = K >> 6;   // chunks of 64

    auto load_chunk = [&](int chunk, int s) {
        uint32_t base = dynb + s * GSTAGE;
        int k0 = chunk * 64;
        #pragma unroll
        for (int i = 0; i < 4; i++) {
            int unit = tid + i * 256;          // 0..1023
            int row  = unit >> 3;              // 0..127
            int c4   = unit & 7;               // 0..7
            uint32_t off = (uint32_t)row * GP + c4 * 16;
            cp16(base + off,          srcA + (size_t)row * K + k0 + c4 * 8);
            cp16(base + GB_OFF + off, srcB + (size_t)row * K + k0 + c4 * 8);
        }
    };

    load_chunk(0, 0); cp_commit();
    load_chunk(1, 1); cp_commit();

    const int arow = wm * 64 + (lane & 15);
    const int acol = (lane >> 4) * 8;
    const int brow = wn * 32 + (lane & 7) + ((lane >> 4) << 3);
    const int bcol = ((lane >> 3) & 1) * 8;

    for (int c = 0; c < NCH; c++) {
        cp_wait1();
        __syncthreads();
        if (c + 2 < NCH) load_chunk(c + 2, (c + 2) % 3);
        cp_commit();

        uint32_t base = dynb + (c % 3) * GSTAGE;
        #pragma unroll
        for (int step = 0; step < 4; step++) {
            int kb = step * 16;
            uint32_t a4[4][4], b4[2][4];
            #pragma unroll
            for (int mt = 0; mt < 4; mt++) {
                uint32_t off = (uint32_t)((arow + mt * 16) * GP + (kb + acol) * 2);
                LDM4(a4[mt], base + off);
            }
            #pragma unroll
            for (int ng = 0; ng < 2; ng++) {
                uint32_t off = (uint32_t)((brow + ng * 16) * GP + (kb + bcol) * 2);
                LDM4(b4[ng], base + GB_OFF + off);
            }
            #pragma unroll
            for (int mt = 0; mt < 4; mt++) {
                #pragma unroll
                for (int nt = 0; nt < 4; nt++) {
                    int ng = nt >> 1, hb = (nt & 1) * 2;
                    MMA16816(acc[mt][nt], a4[mt], b4[ng][hb], b4[ng][hb + 1]);
                }
            }
        }
        __syncthreads();
    }

    // ---- epilogue ----
    #pragma unroll
    for (int mt = 0; mt < 4; mt++) {
        #pragma unroll
        for (int nt = 0; nt < 4; nt++) {
            int row0 = m0 + wm * 64 + mt * 16 + (lane >> 2);
            int col  = n0 + wn * 32 + nt * 8 + (lane & 3) * 2;
            float b0 = bias[col], b1 = bias[col + 1];
            #pragma unroll
            for (int hh = 0; hh < 2; hh++) {
                int r = row0 + hh * 8;
                float o0 = acc[mt][nt][hh * 2 + 0] + b0;
                float o1 = acc[mt][nt][hh * 2 + 1] + b1;
                if (resid) {
                    const float2 rv = *(const float2*)(resid + (size_t)r * N + col);
                    o0 += rv.x; o1 += rv.y;
                }
                *(float2*)(C + (size_t)r * N + col) = make_float2(o0, o1);
            }
        }
    }
}

// ---------------- HMMA split-K GEMM for M=64 middle chain ----------------
#define SKSTAGE 10240
__global__ __launch_bounds__(128, 4)
void hmma_splitk(int N, int K, int kc,
                 const __half* __restrict__ A,
                 const __half* __restrict__ B,
                 float* __restrict__ part) {
    extern __shared__ __align__(16) char dsm[];
    const int tid  = threadIdx.x;
    const int wid  = tid >> 5;
    const int lane = tid & 31;
    const int wm   = wid >> 1;
    const int wn   = wid & 1;
    const int n0   = blockIdx.x * 64;
    const int z    = blockIdx.y;
    const int kb   = z * kc;
    const uint32_t dynb = smem_u32(dsm);

    float acc[2][4][4];
    #pragma unroll
    for (int i = 0; i < 2; i++)
        #pragma unroll
        for (int j = 0; j < 4; j++)
            #pragma unroll
            for (int q = 0; q < 4; q++) acc[i][j][q] = 0.f;

    const __half* srcB = B + (size_t)n0 * K;
    const int NCH = kc >> 5;

    auto load_chunk = [&](int chunk, int s) {
        uint32_t base = dynb + s * SKSTAGE;
        int k0 = kb + chunk * 32;
        int row = tid >> 1;
        int cp  = (tid & 1) * 2;
        uint32_t off = row * 80 + cp * 16;
        cp16(base + off,        A + (size_t)row * K + k0 + cp * 8);
        cp16(base + off + 16,   A + (size_t)row * K + k0 + cp * 8 + 8);
        cp16(base + 5120 + off,      srcB + (size_t)row * K + k0 + cp * 8);
        cp16(base + 5120 + off + 16, srcB + (size_t)row * K + k0 + cp * 8 + 8);
    };

    load_chunk(0, 0); cp_commit();
    if (NCH > 1) load_chunk(1, 1);
    cp_commit();
    if (NCH > 2) load_chunk(2, 2);
    cp_commit();

    const int arow = wm * 32 + (lane & 15);
    const int acol = (lane >> 4) * 8;
    const int brow = wn * 32 + (lane & 7) + ((lane >> 4) << 3);
    const int bcol = ((lane >> 3) & 1) * 8;

    for (int c = 0; c < NCH; c++) {
        cp_wait2();
        __syncthreads();
        if (c + 3 < NCH) load_chunk(c + 3, (c + 3) & 3);
        cp_commit();

        uint32_t base = dynb + (c & 3) * SKSTAGE;
        #pragma unroll
        for (int step = 0; step < 2; step++) {
            int kbb = step * 16;
            uint32_t ah4[2][4], bh4[2][4];
            #pragma unroll
            for (int mt = 0; mt < 2; mt++) {
                uint32_t off = (uint32_t)((arow + mt * 16) * 80 + (kbb + acol) * 2);
                LDM4(ah4[mt], base + off);
            }
            #pragma unroll
            for (int ng = 0; ng < 2; ng++) {
                uint32_t off = (uint32_t)((brow + ng * 16) * 80 + (kbb + bcol) * 2);
                LDM4(bh4[ng], base + 5120 + off);
            }
            #pragma unroll
            for (int mt = 0; mt < 2; mt++) {
                #pragma unroll
                for (int nt = 0; nt < 4; nt++) {
                    int ng = nt >> 1, hb = (nt & 1) * 2;
                    MMA16816(acc[mt][nt], ah4[mt], bh4[ng][hb], bh4[ng][hb + 1]);
                }
            }
        }
    }

    #pragma unroll
    for (int mt = 0; mt < 2; mt++) {
        #pragma unroll
        for (int nt = 0; nt < 4; nt++) {
            int row = wm * 32 + mt * 16 + (lane >> 2);
            int col = n0 + wn * 32 + nt * 8 + (lane & 3) * 2;
            #pragma unroll
            for (int hh = 0; hh < 2; hh++) {
                int r = row + hh * 8;
                *(float2*)(part + ((size_t)z * 64 + r) * N + col)
                    = make_float2(acc[mt][nt][hh * 2 + 0], acc[mt][nt][hh * 2 + 1]);
            }
        }
    }
}

// sum S split-K partials + bias (+relu) (+permute), emit fp32 and/or fp16
__global__ __launch_bounds__(256)
void reduce_bias_act(const float* __restrict__ part, const float* __restrict__ bias,
                     float* __restrict__ outf, __half* __restrict__ outh,
                     int N, int S, int act, int permute) {
    int idx = blockIdx.x * 256 + threadIdx.x;
    int total = 64 * N;
    if (idx >= total) return;
    int m = idx / N, n = idx - m * N;
    float s = 0.f;
    for (int zz = 0; zz < S; zz++) s += part[(size_t)zz * total + idx];
    s += bias[n];
    if (act) s = fmaxf(s, 0.f);
    int oidx = idx;
    if (permute) {
        int b = m >> 3, h = m & 7;
        int na = n >> 9, j = n & 511;
        oidx = ((b * 8 + na)) * 4096 + h * 512 + j;
    }
    if (outf) outf[oidx] = s;
    if (outh) outh[oidx] = __float2half_rn(s);
}

// ---------------- attention 1: one block per (b,h), all 8 anchors ----------------
__global__ __launch_bounds__(256) void attn1_kernel(const float* __restrict__ q_anchor) {
    extern __shared__ float a1s[];
    float* probs   = a1s;                   // [8][2048]
    float* qs      = a1s + 8 * 2048;        // [8][128]
    float* halfbuf = qs + 8 * 128;          // [8][128]
    float* red     = halfbuf + 8 * 128;     // [8 warps][8]
    float* Mv      = red + 64;              // [8]
    float* invS    = Mv + 8;                // [8]
    const int h = blockIdx.x & 7;
    const int b = blockIdx.x >> 3;
    const int tid = threadIdx.x;
    const int warp = tid >> 5, lane = tid & 31;

    for (int i = tid; i < 1024; i += 256) qs[i] = q_anchor[h * 1024 + i];
    __syncthreads();

    float lmax[8];
    #pragma unroll
    for (int a = 0; a < 8; a++) lmax[a] = -1e30f;
    #pragma unroll
    for (int i = 0; i < 8; i++) {
        int n = tid + i * 256;
        const float4* kr = (const float4*)(g_qkv + (((size_t)(b * NQL + n)) * 3 + 1) * AHD + h * DDIM);
        float lg[8];
        #pragma unroll
        for (int a = 0; a < 8; a++) lg[a] = 0.f;
        #pragma unroll
        for (int j = 0; j < 32; j++) {
            float4 kv = kr[j];
            #pragma unroll
            for (int a = 0; a < 8; a++) {
                float4 qv = ((const float4*)(qs + a * 128))[j];
                lg[a] += kv.x*qv.x + kv.y*qv.y + kv.z*qv.z + kv.w*qv.w;
            }
        }
        #pragma unroll
        for (int a = 0; a < 8; a++) {
            float v = lg[a] * SCALE_D;
            probs[a * 2048 + n] = v;
            lmax[a] = fmaxf(lmax[a], v);
        }
    }
    #pragma unroll
    for (int a = 0; a < 8; a++) {
        #pragma unroll
        for (int o = 16; o; o >>= 1) lmax[a] = fmaxf(lmax[a], __shfl_xor_sync(0xffffffffu, lmax[a], o));
    }
    if (lane == 0)
        #pragma unroll
        for (int a = 0; a < 8; a++) red[warp * 8 + a] = lmax[a];
    __syncthreads();
    if (tid < 8) {
        float m = -1e30f;
        #pragma unroll
        for (int w = 0; w < 8; w++) m = fmaxf(m, red[w * 8 + tid]);
        Mv[tid] = m;
    }
    __syncthreads();

    float lsum[8];
    #pragma unroll
    for (int a = 0; a < 8; a++) lsum[a] = 0.f;
    #pragma unroll
    for (int i = 0; i < 8; i++) {
        int n = tid + i * 256;
        #pragma unroll
        for (int a = 0; a < 8; a++) {
            float e = __expf(probs[a * 2048 + n] - Mv[a]);
            probs[a * 2048 + n] = e;
            lsum[a] += e;
        }
    }
    #pragma unroll
    for (int a = 0; a < 8; a++) {
        #pragma unroll
        for (int o = 16; o; o >>= 1) lsum[a] += __shfl_xor_sync(0xffffffffu, lsum[a], o);
    }
    __syncthreads();
    if (lane == 0)
        #pragma unroll
        for (int a = 0; a < 8; a++) red[warp * 8 + a] = lsum[a];
    __syncthreads();
    if (tid < 8) {
        float s = 0.f;
        #pragma unroll
        for (int w = 0; w < 8; w++) s += red[w * 8 + tid];
        invS[tid] = 1.0f / s;
    }
    __syncthreads();

    const int d = tid & 127, hf = tid >> 7;
    float acc[8];
    #pragma unroll
    for (int a = 0; a < 8; a++) acc[a] = 0.f;
    const int nbase = hf * 1024;
    for (int n4 = 0; n4 < 256; n4++) {
        int n = nbase + n4 * 4;
        float4 pv[8];
        #pragma unroll
        for (int a = 0; a < 8; a++) pv[a] = *(const float4*)(probs + a * 2048 + n);
        #pragma unroll
        for (int t = 0; t < 4; t++) {
            float v = g_qkv[(((size_t)(b * NQL + n + t)) * 3 + 2) * AHD + h * DDIM + d];
            #pragma unroll
            for (int a = 0; a < 8; a++) {
                float p = (t == 0) ? pv[a].x : (t == 1) ? pv[a].y : (t == 2) ? pv[a].z : pv[a].w;
                acc[a] += p * v;
            }
        }
    }
    if (hf)
        #pragma unroll
        for (int a = 0; a < 8; a++) halfbuf[a * 128 + d] = acc[a];
    __syncthreads();
    if (!hf)
        #pragma unroll
        for (int a = 0; a < 8; a++)
            g_att1h[(((size_t)(b * 8 + h)) * 8 + a) * 128 + d]
                = __float2half_rn((acc[a] + halfbuf[a * 128 + d]) * invS[a]);
}

// ---------------- attention 2: writes y as fp16 ----------------
__global__ __launch_bounds__(128) void attn2_kernel() {
    const int nc = blockIdx.x;
    const int h  = blockIdx.y;
    const int b  = blockIdx.z;
    const int tid = threadIdx.x;
    __shared__ __align__(16) float kks[8][128];
    __shared__ __align__(16) float ovs[8][128];
    __shared__ float ps[128][9];
    #pragma unroll
    for (int r = 0; r < 8; r++) {
        kks[r][tid] = g_kkb [((size_t)(b * 8 + r)) * AHD + h * 128 + tid];
        ovs[r][tid] = g_out3[((size_t)(b * 8 + r)) * AHD + h * 128 + tid];
    }
    __syncthreads();
    const int n = nc * 128 + tid;
    const float4* qr = (const float4*)(g_qkv + ((size_t)(b * NQL + n)) * 3 * AHD + h * 128);
    float lg[8];
    #pragma unroll
    for (int aa = 0; aa < 8; aa++) lg[aa] = 0.f;
    #pragma unroll
    for (int j = 0; j < 32; j++) {
        float4 qv = qr[j];
        #pragma unroll
        for (int aa = 0; aa < 8; aa++) {
            float4 kv = ((const float4*)kks[aa])[j];
            lg[aa] += qv.x*kv.x + qv.y*kv.y + qv.z*kv.z + qv.w*kv.w;
        }
    }
    float m = -1e30f;
    #pragma unroll
    for (int aa = 0; aa < 8; aa++) { lg[aa] *= SCALE_D; m = fmaxf(m, lg[aa]); }
    float s = 0.f;
    #pragma unroll
    for (int aa = 0; aa < 8; aa++) { lg[aa] = __expf(lg[aa] - m); s += lg[aa]; }
    float inv = 1.0f / s;
    #pragma unroll
    for (int aa = 0; aa < 8; aa++) ps[tid][aa] = lg[aa] * inv;
    __syncthreads();
    for (int i = 0; i < 128; i++) {
        float acc = 0.f;
        #pragma unroll
        for (int aa = 0; aa < 8; aa++) acc += ps[i][aa] * ovs[aa][tid];
        size_t idx = ((size_t)(b * NQL) + nc * 128 + i) * AHD + h * 128 + tid;
        g_yh[idx] = __float2half_rn(acc);
    }
}

// ---------------- host orchestration ----------------
extern "C" void kernel_launch(void* const* d_in, const int* in_sizes, int n_in,
                              void* d_out, int out_size) {
    (void)in_sizes; (void)n_in; (void)out_size;
    const float* inputs   = (const float*)d_in[0];
    const float* ln_g     = (const float*)d_in[1];
    const float* ln_b     = (const float*)d_in[2];
    const float* q_anchor = (const float*)d_in[3];
    const float* W_qkv    = (const float*)d_in[4];
    const float* b_qkv    = (const float*)d_in[5];
    const float* W_an     = (const float*)d_in[6];
    const float* b_an     = (const float*)d_in[7];
    const float* W_n1     = (const float*)d_in[8];
    const float* b_n1     = (const float*)d_in[9];
    const float* W_n2     = (const float*)d_in[10];
    const float* b_n2     = (const float*)d_in[11];
    const float* W_n3     = (const float*)d_in[12];
    const float* b_n3     = (const float*)d_in[13];
    const float* W_k      = (const float*)d_in[14];
    const float* b_k      = (const float*)d_in[15];
    const float* W_o      = (const float*)d_in[16];
    const float* b_o      = (const float*)d_in[17];
    float* out = (float*)d_out;

    float *qkv, *out3, *kk, *part;
    __half *xh, *yh, *wqh, *woh, *want, *wn1t, *wn2t, *wn3t, *wkt;
    __half *att1h, *netinh, *n1h, *n2h, *out3h;
    cudaGetSymbolAddress((void**)&qkv,   g_qkv);
    cudaGetSymbolAddress((void**)&out3,  g_out3);
    cudaGetSymbolAddress((void**)&kk,    g_kkb);
    cudaGetSymbolAddress((void**)&part,  g_part);
    cudaGetSymbolAddress((void**)&xh,    g_xh);
    cudaGetSymbolAddress((void**)&yh,    g_yh);
    cudaGetSymbolAddress((void**)&wqh,   g_wqh);
    cudaGetSymbolAddress((void**)&woh,   g_woh);
    cudaGetSymbolAddress((void**)&want,  g_want);
    cudaGetSymbolAddress((void**)&wn1t,  g_wn1t);
    cudaGetSymbolAddress((void**)&wn2t,  g_wn2t);
    cudaGetSymbolAddress((void**)&wn3t,  g_wn3t);
    cudaGetSymbolAddress((void**)&wkt,   g_wkt);
    cudaGetSymbolAddress((void**)&att1h, g_att1h);
    cudaGetSymbolAddress((void**)&netinh,g_netinh);
    cudaGetSymbolAddress((void**)&n1h,   g_n1h);
    cudaGetSymbolAddress((void**)&n2h,   g_n2h);
    cudaGetSymbolAddress((void**)&out3h, g_out3h);

    static int attr_done = 0;
    if (!attr_done) {
        cudaFuncSetAttribute(gemm_hmma, cudaFuncAttributeMaxDynamicSharedMemorySize, 3 * GSTAGE);
        cudaFuncSetAttribute(hmma_splitk, cudaFuncAttributeMaxDynamicSharedMemorySize, 4 * SKSTAGE);
        cudaFuncSetAttribute(attn1_kernel, cudaFuncAttributeMaxDynamicSharedMemorySize, 74112);
        attr_done = 1;
    }

    // weight conversion (transpose to [N,K] fp16)
    convw_kernel<<<dim3(3072/32, 1024/32), 256>>>(W_qkv, wqh, 1024, 3072);
    convw_kernel<<<dim3(1024/32, 1024/32), 256>>>(W_o,   woh, 1024, 1024);
    convw_kernel<<<dim3(4096/32, 1024/32), 256>>>(W_an,  want, 1024, 4096);
    convw_kernel<<<dim3(1024/32, 4096/32), 256>>>(W_n1,  wn1t, 4096, 1024);
    convw_kernel<<<dim3(4096/32, 1024/32), 256>>>(W_n2,  wn2t, 1024, 4096);
    convw_kernel<<<dim3(1024/32, 4096/32), 256>>>(W_n3,  wn3t, 4096, 1024);
    convw_kernel<<<dim3(1024/32, 1024/32), 256>>>(W_k,   wkt,  1024, 1024);

    // LN -> fp16
    ln_kernel<<<MROWS, 256>>>(inputs, ln_g, ln_b);

    // qkv = x @ W_qkv + b_qkv     (HMMA, 16384 x 3072 x 1024)
    gemm_hmma<<<dim3(3072/128, MROWS/128), 256, 3*GSTAGE>>>(
        3072, 1024, xh, wqh, b_qkv, nullptr, qkv);

    // attention 1 -> fp16 att1h
    attn1_kernel<<<BB * HH, 256, 74112>>>(q_anchor);

    // middle MLP chain (fp16 HMMA split-K)
    hmma_splitk<<<dim3(4096/64, 8), 128, 4*SKSTAGE>>>(4096, 1024, 128, att1h, want, part);
    reduce_bias_act<<<(64*4096+255)/256, 256>>>(part, b_an, nullptr, netinh, 4096, 8, 1, 1);
    hmma_splitk<<<dim3(1024/64, 16), 128, 4*SKSTAGE>>>(1024, 4096, 256, netinh, wn1t, part);
    reduce_bias_act<<<(64*1024+255)/256, 256>>>(part, b_n1, nullptr, n1h, 1024, 16, 0, 0);
    hmma_splitk<<<dim3(4096/64, 8), 128, 4*SKSTAGE>>>(4096, 1024, 128, n1h, wn2t, part);
    reduce_bias_act<<<(64*4096+255)/256, 256>>>(part, b_n2, nullptr, n2h, 4096, 8, 1, 0);
    hmma_splitk<<<dim3(1024/64, 16), 128, 4*SKSTAGE>>>(1024, 4096, 256, n2h, wn3t, part);
    reduce_bias_act<<<(64*1024+255)/256, 256>>>(part, b_n3, out3, out3h, 1024, 16, 0, 0);
    hmma_splitk<<<dim3(1024/64, 8), 128, 4*SKSTAGE>>>(1024, 1024, 128, out3h, wkt, part);
    reduce_bias_act<<<(64*1024+255)/256, 256>>>(part, b_k, kk, nullptr, 1024, 8, 0, 0);

    // attention 2 (-> fp16 y)
    attn2_kernel<<<dim3(NQL/128, HH, BB), 128>>>();

    // out = y @ W_o + b_o + inputs   (HMMA, 16384 x 1024 x 1024)
    gemm_hmma<<<dim3(1024/128, MROWS/128), 256, 3*GSTAGE>>>(
        1024, 1024, yh, woh, b_o, inputs, out);
}